// round 9
// baseline (speedup 1.0000x reference)
#include <cuda_runtime.h>
#include <cuda_bf16.h>
#include <cuda_fp16.h>
#include <cstdint>

#define NMAX 50000
#define EMAX 800000
#define DIMH 128
#define NHEADS 8
#define HEADDIM 16

// ---------------------------------------------------------------------------
// Scratch (fp16 QKV to halve gather traffic; fp32 elsewhere)
// ---------------------------------------------------------------------------
__device__ __half g_Q[(size_t)NMAX * DIMH];
__device__ __half g_K[(size_t)NMAX * DIMH];
__device__ __half g_V[(size_t)NMAX * DIMH];
__device__ float  g_ex[(size_t)EMAX * NHEADS];
__device__ float  g_segsum[(size_t)NMAX * NHEADS];

// ---------------------------------------------------------------------------
// Helpers
// ---------------------------------------------------------------------------
__device__ __forceinline__ void red_add_v4(float* addr, float4 v) {
    asm volatile("red.global.add.v4.f32 [%0], {%1, %2, %3, %4};"
                 :: "l"(addr), "f"(v.x), "f"(v.y), "f"(v.z), "f"(v.w) : "memory");
}
__device__ __forceinline__ void red_add_f32(float* addr, float v) {
    asm volatile("red.global.add.f32 [%0], %1;" :: "l"(addr), "f"(v) : "memory");
}
__device__ __forceinline__ uint32_t f32_to_tf32(float f) {
    uint32_t r;
    asm("cvt.rna.tf32.f32 %0, %1;" : "=r"(r) : "f"(f));
    return r;
}
__device__ __forceinline__ void mma_tf32(float (&c)[4],
                                         uint32_t a0, uint32_t a1,
                                         uint32_t a2, uint32_t a3,
                                         uint32_t b0, uint32_t b1) {
    asm volatile("mma.sync.aligned.m16n8k8.row.col.f32.tf32.tf32.f32 "
                 "{%0,%1,%2,%3}, {%4,%5,%6,%7}, {%8,%9}, {%0,%1,%2,%3};"
                 : "+f"(c[0]), "+f"(c[1]), "+f"(c[2]), "+f"(c[3])
                 : "r"(a0), "r"(a1), "r"(a2), "r"(a3), "r"(b0), "r"(b1));
}

// ---------------------------------------------------------------------------
// Kernel 1: tf32 mma.sync GEMM, 2D warp tiling (4M x 2N warps, 32x64 tiles).
// Shared k-columns permuted within 8-groups ([0,4,1,5,2,6,3,7]) so fragment
// pairs (k=t, k=t+4) are adjacent -> LDS.64 fragment loads.
// Q-branch CTAs also zero their out_h slice + segsum (fused init).
// ---------------------------------------------------------------------------
#define BK 32
#define SPAD 36

__global__ __launch_bounds__(256)
void gemm_qkv_mma(const float* __restrict__ x,
                  const float* __restrict__ WQ, const float* __restrict__ bQ,
                  const float* __restrict__ WK, const float* __restrict__ bK,
                  const float* __restrict__ WV, const float* __restrict__ bV,
                  int n, float* __restrict__ out_h) {
    const float* W;
    const float* bias;
    __half* out;
    if (blockIdx.y == 0)      { W = WQ; bias = bQ; out = g_Q; }
    else if (blockIdx.y == 1) { W = WK; bias = bK; out = g_K; }
    else                      { W = WV; bias = bV; out = g_V; }

    __shared__ uint32_t As[128][SPAD];
    __shared__ uint32_t Bs[128][SPAD];

    const int tid  = threadIdx.x;
    const int wid  = tid >> 5;
    const int lane = tid & 31;
    const int g    = lane >> 2;
    const int t    = lane & 3;
    const int row0 = blockIdx.x * 128;
    const int wm   = wid & 3;        // M group: rows [wm*32, wm*32+32)
    const int wn   = wid >> 2;       // N group: cols [wn*64, wn*64+64)

    // --- fused init: Q-branch zeroes out_h rows [row0, row0+128) and segsum
    if (blockIdx.y == 0) {
        float4 z = make_float4(0.f, 0.f, 0.f, 0.f);
#pragma unroll
        for (int i = 0; i < 16; i++) {
            int idx = tid + i * 256;
            int r   = row0 + (idx >> 5);
            if (r < n)
                *(float4*)(out_h + (size_t)r * DIMH + (idx & 31) * 4) = z;
        }
        {
            int r = row0 + (tid >> 1);
            if (r < n)
                *(float4*)(g_segsum + (size_t)r * NHEADS + (tid & 1) * 4) = z;
        }
    }

    float acc[2][8][4];
#pragma unroll
    for (int mi = 0; mi < 2; mi++)
#pragma unroll
        for (int nt = 0; nt < 8; nt++)
#pragma unroll
            for (int j = 0; j < 4; j++) acc[mi][nt][j] = 0.0f;

    for (int kc = 0; kc < DIMH; kc += BK) {
        // Load tiles; permuted col index: for float4 c4, element j:
        //   smem col = (c4>>1)*8 + 2*j + (c4&1)
#pragma unroll
        for (int i = 0; i < 4; i++) {
            int idx = tid + i * 256;
            int row = idx >> 3;
            int c4  = idx & 7;
            int cb  = (c4 >> 1) * 8 + (c4 & 1);
            int gr  = row0 + row;
            float4 a = make_float4(0.f, 0.f, 0.f, 0.f);
            if (gr < n) a = *(const float4*)(x + (size_t)gr * DIMH + kc + c4 * 4);
            As[row][cb + 0] = f32_to_tf32(a.x);
            As[row][cb + 2] = f32_to_tf32(a.y);
            As[row][cb + 4] = f32_to_tf32(a.z);
            As[row][cb + 6] = f32_to_tf32(a.w);

            float4 w = *(const float4*)(W + (size_t)row * DIMH + kc + c4 * 4);
            Bs[row][cb + 0] = f32_to_tf32(w.x);
            Bs[row][cb + 2] = f32_to_tf32(w.y);
            Bs[row][cb + 4] = f32_to_tf32(w.z);
            Bs[row][cb + 6] = f32_to_tf32(w.w);
        }
        __syncthreads();

#pragma unroll
        for (int ks = 0; ks < BK / 8; ks++) {
            int k0 = ks * 8 + 2 * t;
            // A fragment pairs: (a0,a2) from row g, (a1,a3) from row g+8
            uint2 aP[2][2];
#pragma unroll
            for (int mi = 0; mi < 2; mi++) {
                aP[mi][0] = *(const uint2*)&As[wm * 32 + mi * 16 + g][k0];
                aP[mi][1] = *(const uint2*)&As[wm * 32 + mi * 16 + g + 8][k0];
            }
            uint2 bP[8];
#pragma unroll
            for (int nt = 0; nt < 8; nt++)
                bP[nt] = *(const uint2*)&Bs[wn * 64 + nt * 8 + g][k0];

#pragma unroll
            for (int mi = 0; mi < 2; mi++)
#pragma unroll
                for (int nt = 0; nt < 8; nt++)
                    mma_tf32(acc[mi][nt],
                             aP[mi][0].x, aP[mi][1].x,
                             aP[mi][0].y, aP[mi][1].y,
                             bP[nt].x, bP[nt].y);
        }
        __syncthreads();
    }

    // Epilogue: add bias, convert to fp16, store half2
#pragma unroll
    for (int mi = 0; mi < 2; mi++) {
        int r0 = row0 + wm * 32 + mi * 16 + g;
        int r1 = r0 + 8;
#pragma unroll
        for (int nt = 0; nt < 8; nt++) {
            int c = wn * 64 + nt * 8 + 2 * t;
            float bx = __ldg(bias + c), by = __ldg(bias + c + 1);
            if (r0 < n) {
                __half2 v0 = __floats2half2_rn(acc[mi][nt][0] + bx,
                                               acc[mi][nt][1] + by);
                *(__half2*)(out + (size_t)r0 * DIMH + c) = v0;
            }
            if (r1 < n) {
                __half2 v1 = __floats2half2_rn(acc[mi][nt][2] + bx,
                                               acc[mi][nt][3] + by);
                *(__half2*)(out + (size_t)r1 * DIMH + c) = v1;
            }
        }
    }
}

// ---------------------------------------------------------------------------
// Kernel 2 (FUSED): warp per edge.  fp16 Q/K/V loads, fp32 math, REDG out.
// ---------------------------------------------------------------------------
__global__ __launch_bounds__(256)
void fused_edge(const int* __restrict__ ei,
                const float* __restrict__ ebias,
                int E_, float* __restrict__ out_h) {
    int e    = (blockIdx.x * blockDim.x + threadIdx.x) >> 5;
    int lane = threadIdx.x & 31;
    if (e >= E_) return;

    int src = __ldg(ei + e);
    int dst = __ldg(ei + E_ + e);

    __half2 q2[2], k2[2];
    *(uint2*)q2 = *(const uint2*)(g_Q + (size_t)dst * DIMH + lane * 4);
    *(uint2*)k2 = *(const uint2*)(g_K + (size_t)src * DIMH + lane * 4);

    float2 qa = __half22float2(q2[0]), qb = __half22float2(q2[1]);
    float2 ka = __half22float2(k2[0]), kb = __half22float2(k2[1]);

    float p = qa.x * ka.x + qa.y * ka.y + qb.x * kb.x + qb.y * kb.y;
    p += __shfl_xor_sync(0xffffffffu, p, 1);
    p += __shfl_xor_sync(0xffffffffu, p, 2);

    int h = lane >> 2;
    float bias = __ldg(ebias + (size_t)e * NHEADS + h);
    float ex = __expf(p * 0.25f + bias);

    if ((lane & 3) == 0) {
        g_ex[(size_t)e * NHEADS + h] = ex;
        red_add_f32(g_segsum + (size_t)dst * NHEADS + h, ex);
    }

    __half2 v2[2];
    *(uint2*)v2 = *(const uint2*)(g_V + (size_t)src * DIMH + lane * 4);
    float2 va = __half22float2(v2[0]), vb = __half22float2(v2[1]);

    float4 v = make_float4(va.x * ex, va.y * ex, vb.x * ex, vb.y * ex);
    red_add_v4(out_h + (size_t)dst * DIMH + lane * 4, v);
}

// ---------------------------------------------------------------------------
// Kernel 3 (merged finalize): normalize h + write alpha
// ---------------------------------------------------------------------------
__global__ void finalize(const int* __restrict__ ei, int E_, int n,
                         float* __restrict__ out_h,
                         float* __restrict__ out_alpha) {
    int t = blockIdx.x * blockDim.x + threadIdx.x;

    if (t < n * 32) {
        int i = t >> 5;
        int c4 = t & 31;
        float s = g_segsum[(size_t)i * NHEADS + (c4 >> 2)];
        float inv = 1.0f / s;
        float4 v = *(float4*)(out_h + (size_t)i * DIMH + c4 * 4);
        v.x *= inv; v.y *= inv; v.z *= inv; v.w *= inv;
        *(float4*)(out_h + (size_t)i * DIMH + c4 * 4) = v;
    }

    if (t < E_) {
        int dst = __ldg(ei + E_ + t);
        float4 e0 = *(const float4*)(g_ex + (size_t)t * NHEADS);
        float4 e1 = *(const float4*)(g_ex + (size_t)t * NHEADS + 4);
        float4 s0 = *(const float4*)(g_segsum + (size_t)dst * NHEADS);
        float4 s1 = *(const float4*)(g_segsum + (size_t)dst * NHEADS + 4);

        e0.x /= s0.x; e0.y /= s0.y; e0.z /= s0.z; e0.w /= s0.w;
        e1.x /= s1.x; e1.y /= s1.y; e1.z /= s1.z; e1.w /= s1.w;

        *(float4*)(out_alpha + (size_t)t * NHEADS)     = e0;
        *(float4*)(out_alpha + (size_t)t * NHEADS + 4) = e1;
    }
}

// ---------------------------------------------------------------------------
// Launch
// ---------------------------------------------------------------------------
extern "C" void kernel_launch(void* const* d_in, const int* in_sizes, int n_in,
                              void* d_out, int out_size) {
    const float* x     = (const float*)d_in[0];
    const int*   ei    = (const int*)d_in[1];
    const float* ebias = (const float*)d_in[2];
    const float* WQ    = (const float*)d_in[3];
    const float* bQ    = (const float*)d_in[4];
    const float* WK    = (const float*)d_in[5];
    const float* bK    = (const float*)d_in[6];
    const float* WV    = (const float*)d_in[7];
    const float* bV    = (const float*)d_in[8];

    int n = in_sizes[0] / DIMH;     // 50000
    int e = in_sizes[1] / 2;        // 800000

    float* out_h = (float*)d_out;
    float* out_alpha = out_h + (size_t)n * DIMH;

    // 1) QKV projections (tf32 mma.sync, 2D warp tiling) + fused zero-init
    {
        dim3 grid((n + 127) / 128, 3);
        gemm_qkv_mma<<<grid, 256>>>(x, WQ, bQ, WK, bK, WV, bV, n, out_h);
    }
    // 2) fused edge pass
    {
        long long threads = (long long)e * 32;
        int blocks = (int)((threads + 255) / 256);
        fused_edge<<<blocks, 256>>>(ei, ebias, e, out_h);
    }
    // 3) finalize: normalize h + write alpha
    {
        int total = n * 32 > e ? n * 32 : e;
        int blocks = (total + 255) / 256;
        finalize<<<blocks, 256>>>(ei, e, n, out_h, out_alpha);
    }
}

// round 10
// speedup vs baseline: 1.0495x; 1.0495x over previous
#include <cuda_runtime.h>
#include <cuda_bf16.h>
#include <cuda_fp16.h>
#include <cstdint>

#define NMAX 50000
#define EMAX 800000
#define DIMH 128
#define NHEADS 8
#define HEADDIM 16

// ---------------------------------------------------------------------------
// Scratch (fp16 QKV to halve gather traffic; fp32 elsewhere)
// ---------------------------------------------------------------------------
__device__ __half g_Q[(size_t)NMAX * DIMH];
__device__ __half g_K[(size_t)NMAX * DIMH];
__device__ __half g_V[(size_t)NMAX * DIMH];
__device__ float  g_ex[(size_t)EMAX * NHEADS];
__device__ float  g_segsum[(size_t)NMAX * NHEADS];

// ---------------------------------------------------------------------------
// Helpers
// ---------------------------------------------------------------------------
__device__ __forceinline__ void red_add_v4(float* addr, float4 v) {
    asm volatile("red.global.add.v4.f32 [%0], {%1, %2, %3, %4};"
                 :: "l"(addr), "f"(v.x), "f"(v.y), "f"(v.z), "f"(v.w) : "memory");
}
__device__ __forceinline__ void red_add_f32(float* addr, float v) {
    asm volatile("red.global.add.f32 [%0], %1;" :: "l"(addr), "f"(v) : "memory");
}
__device__ __forceinline__ uint32_t f32_to_tf32(float f) {
    uint32_t r;
    asm("cvt.rna.tf32.f32 %0, %1;" : "=r"(r) : "f"(f));
    return r;
}
__device__ __forceinline__ void mma_tf32(float (&c)[4],
                                         uint32_t a0, uint32_t a1,
                                         uint32_t a2, uint32_t a3,
                                         uint32_t b0, uint32_t b1) {
    asm volatile("mma.sync.aligned.m16n8k8.row.col.f32.tf32.tf32.f32 "
                 "{%0,%1,%2,%3}, {%4,%5,%6,%7}, {%8,%9}, {%0,%1,%2,%3};"
                 : "+f"(c[0]), "+f"(c[1]), "+f"(c[2]), "+f"(c[3])
                 : "r"(a0), "r"(a1), "r"(a2), "r"(a3), "r"(b0), "r"(b1));
}

// ---------------------------------------------------------------------------
// Kernel 1: tf32 mma.sync GEMM.
// 2D warp tiling (4M x 2N warps -> 32x64 warp tiles) with the PROVEN R8
// smem layout (As[row][k], SPAD=36, conflict-free 32-bit fragment loads).
// Q-branch CTAs also zero their out_h slice + segsum (fused init).
// ---------------------------------------------------------------------------
#define BK 32
#define SPAD 36

__global__ __launch_bounds__(256)
void gemm_qkv_mma(const float* __restrict__ x,
                  const float* __restrict__ WQ, const float* __restrict__ bQ,
                  const float* __restrict__ WK, const float* __restrict__ bK,
                  const float* __restrict__ WV, const float* __restrict__ bV,
                  int n, float* __restrict__ out_h) {
    const float* W;
    const float* bias;
    __half* out;
    if (blockIdx.y == 0)      { W = WQ; bias = bQ; out = g_Q; }
    else if (blockIdx.y == 1) { W = WK; bias = bK; out = g_K; }
    else                      { W = WV; bias = bV; out = g_V; }

    __shared__ uint32_t As[128][SPAD];
    __shared__ uint32_t Bs[128][SPAD];

    const int tid  = threadIdx.x;
    const int wid  = tid >> 5;
    const int lane = tid & 31;
    const int g    = lane >> 2;
    const int t    = lane & 3;
    const int row0 = blockIdx.x * 128;
    const int wm   = wid & 3;        // M group: rows [wm*32, wm*32+32)
    const int wn   = wid >> 2;       // N group: cols [wn*64, wn*64+64)

    // --- fused init: Q-branch zeroes out_h rows [row0, row0+128) and segsum
    if (blockIdx.y == 0) {
        float4 z = make_float4(0.f, 0.f, 0.f, 0.f);
#pragma unroll
        for (int i = 0; i < 16; i++) {
            int idx = tid + i * 256;
            int r   = row0 + (idx >> 5);
            if (r < n)
                *(float4*)(out_h + (size_t)r * DIMH + (idx & 31) * 4) = z;
        }
        {
            int r = row0 + (tid >> 1);
            if (r < n)
                *(float4*)(g_segsum + (size_t)r * NHEADS + (tid & 1) * 4) = z;
        }
    }

    float acc[2][8][4];
#pragma unroll
    for (int mi = 0; mi < 2; mi++)
#pragma unroll
        for (int nt = 0; nt < 8; nt++)
#pragma unroll
            for (int j = 0; j < 4; j++) acc[mi][nt][j] = 0.0f;

    for (int kc = 0; kc < DIMH; kc += BK) {
        // Load A (x rows, zero-padded) and B (W rows): 128x32 each (R8 layout)
#pragma unroll
        for (int i = 0; i < 4; i++) {
            int idx = tid + i * 256;
            int row = idx >> 3;
            int c4  = idx & 7;
            int gr  = row0 + row;
            float4 a = make_float4(0.f, 0.f, 0.f, 0.f);
            if (gr < n) a = *(const float4*)(x + (size_t)gr * DIMH + kc + c4 * 4);
            As[row][c4 * 4 + 0] = f32_to_tf32(a.x);
            As[row][c4 * 4 + 1] = f32_to_tf32(a.y);
            As[row][c4 * 4 + 2] = f32_to_tf32(a.z);
            As[row][c4 * 4 + 3] = f32_to_tf32(a.w);

            float4 w = *(const float4*)(W + (size_t)row * DIMH + kc + c4 * 4);
            Bs[row][c4 * 4 + 0] = f32_to_tf32(w.x);
            Bs[row][c4 * 4 + 1] = f32_to_tf32(w.y);
            Bs[row][c4 * 4 + 2] = f32_to_tf32(w.z);
            Bs[row][c4 * 4 + 3] = f32_to_tf32(w.w);
        }
        __syncthreads();

#pragma unroll
        for (int ks = 0; ks < BK / 8; ks++) {
            int k0 = ks * 8;
            uint32_t a[2][4];
#pragma unroll
            for (int mi = 0; mi < 2; mi++) {
                int r = wm * 32 + mi * 16 + g;
                a[mi][0] = As[r][k0 + t];
                a[mi][1] = As[r + 8][k0 + t];
                a[mi][2] = As[r][k0 + t + 4];
                a[mi][3] = As[r + 8][k0 + t + 4];
            }
            uint32_t b[8][2];
#pragma unroll
            for (int nt = 0; nt < 8; nt++) {
                int r = wn * 64 + nt * 8 + g;
                b[nt][0] = Bs[r][k0 + t];
                b[nt][1] = Bs[r][k0 + t + 4];
            }
#pragma unroll
            for (int mi = 0; mi < 2; mi++)
#pragma unroll
                for (int nt = 0; nt < 8; nt++)
                    mma_tf32(acc[mi][nt],
                             a[mi][0], a[mi][1], a[mi][2], a[mi][3],
                             b[nt][0], b[nt][1]);
        }
        __syncthreads();
    }

    // Epilogue: add bias, convert to fp16, store half2
#pragma unroll
    for (int mi = 0; mi < 2; mi++) {
        int r0 = row0 + wm * 32 + mi * 16 + g;
        int r1 = r0 + 8;
#pragma unroll
        for (int nt = 0; nt < 8; nt++) {
            int c = wn * 64 + nt * 8 + 2 * t;
            float bx = __ldg(bias + c), by = __ldg(bias + c + 1);
            if (r0 < n) {
                __half2 v0 = __floats2half2_rn(acc[mi][nt][0] + bx,
                                               acc[mi][nt][1] + by);
                *(__half2*)(out + (size_t)r0 * DIMH + c) = v0;
            }
            if (r1 < n) {
                __half2 v1 = __floats2half2_rn(acc[mi][nt][2] + bx,
                                               acc[mi][nt][3] + by);
                *(__half2*)(out + (size_t)r1 * DIMH + c) = v1;
            }
        }
    }
}

// ---------------------------------------------------------------------------
// Kernel 2 (FUSED): warp per edge.  fp16 Q/K/V loads, fp32 math, REDG out.
// ---------------------------------------------------------------------------
__global__ __launch_bounds__(256)
void fused_edge(const int* __restrict__ ei,
                const float* __restrict__ ebias,
                int E_, float* __restrict__ out_h) {
    int e    = (blockIdx.x * blockDim.x + threadIdx.x) >> 5;
    int lane = threadIdx.x & 31;
    if (e >= E_) return;

    int src = __ldg(ei + e);
    int dst = __ldg(ei + E_ + e);

    __half2 q2[2], k2[2];
    *(uint2*)q2 = *(const uint2*)(g_Q + (size_t)dst * DIMH + lane * 4);
    *(uint2*)k2 = *(const uint2*)(g_K + (size_t)src * DIMH + lane * 4);

    float2 qa = __half22float2(q2[0]), qb = __half22float2(q2[1]);
    float2 ka = __half22float2(k2[0]), kb = __half22float2(k2[1]);

    float p = qa.x * ka.x + qa.y * ka.y + qb.x * kb.x + qb.y * kb.y;
    p += __shfl_xor_sync(0xffffffffu, p, 1);
    p += __shfl_xor_sync(0xffffffffu, p, 2);

    int h = lane >> 2;
    float bias = __ldg(ebias + (size_t)e * NHEADS + h);
    float ex = __expf(p * 0.25f + bias);

    if ((lane & 3) == 0) {
        g_ex[(size_t)e * NHEADS + h] = ex;
        red_add_f32(g_segsum + (size_t)dst * NHEADS + h, ex);
    }

    __half2 v2[2];
    *(uint2*)v2 = *(const uint2*)(g_V + (size_t)src * DIMH + lane * 4);
    float2 va = __half22float2(v2[0]), vb = __half22float2(v2[1]);

    float4 v = make_float4(va.x * ex, va.y * ex, vb.x * ex, vb.y * ex);
    red_add_v4(out_h + (size_t)dst * DIMH + lane * 4, v);
}

// ---------------------------------------------------------------------------
// Kernel 3 (merged finalize): normalize h + write alpha
// ---------------------------------------------------------------------------
__global__ void finalize(const int* __restrict__ ei, int E_, int n,
                         float* __restrict__ out_h,
                         float* __restrict__ out_alpha) {
    int t = blockIdx.x * blockDim.x + threadIdx.x;

    if (t < n * 32) {
        int i = t >> 5;
        int c4 = t & 31;
        float s = g_segsum[(size_t)i * NHEADS + (c4 >> 2)];
        float inv = 1.0f / s;
        float4 v = *(float4*)(out_h + (size_t)i * DIMH + c4 * 4);
        v.x *= inv; v.y *= inv; v.z *= inv; v.w *= inv;
        *(float4*)(out_h + (size_t)i * DIMH + c4 * 4) = v;
    }

    if (t < E_) {
        int dst = __ldg(ei + E_ + t);
        float4 e0 = *(const float4*)(g_ex + (size_t)t * NHEADS);
        float4 e1 = *(const float4*)(g_ex + (size_t)t * NHEADS + 4);
        float4 s0 = *(const float4*)(g_segsum + (size_t)dst * NHEADS);
        float4 s1 = *(const float4*)(g_segsum + (size_t)dst * NHEADS + 4);

        e0.x /= s0.x; e0.y /= s0.y; e0.z /= s0.z; e0.w /= s0.w;
        e1.x /= s1.x; e1.y /= s1.y; e1.z /= s1.z; e1.w /= s1.w;

        *(float4*)(out_alpha + (size_t)t * NHEADS)     = e0;
        *(float4*)(out_alpha + (size_t)t * NHEADS + 4) = e1;
    }
}

// ---------------------------------------------------------------------------
// Launch
// ---------------------------------------------------------------------------
extern "C" void kernel_launch(void* const* d_in, const int* in_sizes, int n_in,
                              void* d_out, int out_size) {
    const float* x     = (const float*)d_in[0];
    const int*   ei    = (const int*)d_in[1];
    const float* ebias = (const float*)d_in[2];
    const float* WQ    = (const float*)d_in[3];
    const float* bQ    = (const float*)d_in[4];
    const float* WK    = (const float*)d_in[5];
    const float* bK    = (const float*)d_in[6];
    const float* WV    = (const float*)d_in[7];
    const float* bV    = (const float*)d_in[8];

    int n = in_sizes[0] / DIMH;     // 50000
    int e = in_sizes[1] / 2;        // 800000

    float* out_h = (float*)d_out;
    float* out_alpha = out_h + (size_t)n * DIMH;

    // 1) QKV projections (tf32 mma.sync, 2D warp tiling) + fused zero-init
    {
        dim3 grid((n + 127) / 128, 3);
        gemm_qkv_mma<<<grid, 256>>>(x, WQ, bQ, WK, bK, WV, bV, n, out_h);
    }
    // 2) fused edge pass
    {
        long long threads = (long long)e * 32;
        int blocks = (int)((threads + 255) / 256);
        fused_edge<<<blocks, 256>>>(ei, ebias, e, out_h);
    }
    // 3) finalize: normalize h + write alpha
    {
        int total = n * 32 > e ? n * 32 : e;
        int blocks = (total + 255) / 256;
        finalize<<<blocks, 256>>>(ei, e, n, out_h, out_alpha);
    }
}

// round 11
// speedup vs baseline: 1.1085x; 1.0562x over previous
#include <cuda_runtime.h>
#include <cuda_bf16.h>
#include <cuda_fp16.h>
#include <cstdint>

#define NMAX 50000
#define EMAX 800000
#define DIMH 128
#define NHEADS 8
#define HEADDIM 16

// ---------------------------------------------------------------------------
// Scratch (fp16 QKV to halve gather traffic; fp32 elsewhere)
// ---------------------------------------------------------------------------
__device__ __half g_Q[(size_t)NMAX * DIMH];
__device__ __half g_K[(size_t)NMAX * DIMH];
__device__ __half g_V[(size_t)NMAX * DIMH];
__device__ float  g_ex[(size_t)EMAX * NHEADS];
__device__ float  g_segsum[(size_t)NMAX * NHEADS];

// ---------------------------------------------------------------------------
// Helpers
// ---------------------------------------------------------------------------
__device__ __forceinline__ void red_add_v4(float* addr, float4 v) {
    asm volatile("red.global.add.v4.f32 [%0], {%1, %2, %3, %4};"
                 :: "l"(addr), "f"(v.x), "f"(v.y), "f"(v.z), "f"(v.w) : "memory");
}
__device__ __forceinline__ void red_add_f32(float* addr, float v) {
    asm volatile("red.global.add.f32 [%0], %1;" :: "l"(addr), "f"(v) : "memory");
}
// fp16 mma m16n8k16: A row-major (4 x half2), B col-major (2 x half2), C fp32
__device__ __forceinline__ void mma_f16(float (&c)[4],
                                        uint32_t a0, uint32_t a1,
                                        uint32_t a2, uint32_t a3,
                                        uint32_t b0, uint32_t b1) {
    asm volatile("mma.sync.aligned.m16n8k16.row.col.f32.f16.f16.f32 "
                 "{%0,%1,%2,%3}, {%4,%5,%6,%7}, {%8,%9}, {%0,%1,%2,%3};"
                 : "+f"(c[0]), "+f"(c[1]), "+f"(c[2]), "+f"(c[3])
                 : "r"(a0), "r"(a1), "r"(a2), "r"(a3), "r"(b0), "r"(b1));
}
__device__ __forceinline__ uint32_t pack_half2(float x, float y) {
    __half2 h = __floats2half2_rn(x, y);
    return *(uint32_t*)&h;
}

// ---------------------------------------------------------------------------
// Kernel 1: fp16 mma.sync GEMM (m16n8k16).  out(fp16) = x @ W^T + b.
// 2D warp tiling: 4M x 2N warps -> 32x64 warp tiles.  BK=64 halves.
// Tile layout: [128 rows][36 words] (word = half2 along K); stride%32==4 ->
// fragment reads bank = 4g+t (all distinct, conflict-free); fill writes cover
// one full 16-uint2 row per 16-lane phase (banks 0..31 once, conflict-free).
// Q-branch CTAs also zero their out_h slice + segsum (fused init).
// ---------------------------------------------------------------------------
#define BKH 64          // K elements (halves) per chunk
#define SPADW 36        // words per row (32 data + 4 pad)

__global__ __launch_bounds__(256)
void gemm_qkv_mma(const float* __restrict__ x,
                  const float* __restrict__ WQ, const float* __restrict__ bQ,
                  const float* __restrict__ WK, const float* __restrict__ bK,
                  const float* __restrict__ WV, const float* __restrict__ bV,
                  int n, float* __restrict__ out_h) {
    const float* W;
    const float* bias;
    __half* out;
    if (blockIdx.y == 0)      { W = WQ; bias = bQ; out = g_Q; }
    else if (blockIdx.y == 1) { W = WK; bias = bK; out = g_K; }
    else                      { W = WV; bias = bV; out = g_V; }

    __shared__ uint32_t As[128][SPADW];
    __shared__ uint32_t Bs[128][SPADW];

    const int tid  = threadIdx.x;
    const int wid  = tid >> 5;
    const int lane = tid & 31;
    const int g    = lane >> 2;
    const int t    = lane & 3;
    const int row0 = blockIdx.x * 128;
    const int wm   = wid & 3;        // M group: rows [wm*32, wm*32+32)
    const int wn   = wid >> 2;       // N group: cols [wn*64, wn*64+64)

    // --- fused init: Q-branch zeroes out_h rows [row0, row0+128) and segsum
    if (blockIdx.y == 0) {
        float4 z = make_float4(0.f, 0.f, 0.f, 0.f);
#pragma unroll
        for (int i = 0; i < 16; i++) {
            int idx = tid + i * 256;
            int r   = row0 + (idx >> 5);
            if (r < n)
                *(float4*)(out_h + (size_t)r * DIMH + (idx & 31) * 4) = z;
        }
        {
            int r = row0 + (tid >> 1);
            if (r < n)
                *(float4*)(g_segsum + (size_t)r * NHEADS + (tid & 1) * 4) = z;
        }
    }

    float acc[2][8][4];
#pragma unroll
    for (int mi = 0; mi < 2; mi++)
#pragma unroll
        for (int nt = 0; nt < 8; nt++)
#pragma unroll
            for (int j = 0; j < 4; j++) acc[mi][nt][j] = 0.0f;

    for (int kc = 0; kc < DIMH; kc += BKH) {
        // Fill A (x rows, fp32->fp16) and B (W rows): 128 rows x 16 float4.
        // u2 index: row = u2>>4, c = u2&15 -> halves [4c,4c+4) = words 2c,2c+1
#pragma unroll
        for (int i = 0; i < 8; i++) {
            int u2  = tid + i * 256;         // 0..2047
            int row = u2 >> 4;
            int c   = u2 & 15;
            int gr  = row0 + row;
            float4 a = make_float4(0.f, 0.f, 0.f, 0.f);
            if (gr < n) a = *(const float4*)(x + (size_t)gr * DIMH + kc + c * 4);
            uint2 ap = make_uint2(pack_half2(a.x, a.y), pack_half2(a.z, a.w));
            *(uint2*)&As[row][c * 2] = ap;

            float4 w = *(const float4*)(W + (size_t)row * DIMH + kc + c * 4);
            uint2 wp = make_uint2(pack_half2(w.x, w.y), pack_half2(w.z, w.w));
            *(uint2*)&Bs[row][c * 2] = wp;
        }
        __syncthreads();

#pragma unroll
        for (int ks = 0; ks < BKH / 16; ks++) {
            int wk = ks * 8;                 // word offset of this k16 step
            uint32_t a[2][4];
#pragma unroll
            for (int mi = 0; mi < 2; mi++) {
                int r = wm * 32 + mi * 16 + g;
                a[mi][0] = As[r][wk + t];
                a[mi][1] = As[r + 8][wk + t];
                a[mi][2] = As[r][wk + t + 4];
                a[mi][3] = As[r + 8][wk + t + 4];
            }
            uint32_t b[8][2];
#pragma unroll
            for (int nt = 0; nt < 8; nt++) {
                int r = wn * 64 + nt * 8 + g;
                b[nt][0] = Bs[r][wk + t];
                b[nt][1] = Bs[r][wk + t + 4];
            }
#pragma unroll
            for (int mi = 0; mi < 2; mi++)
#pragma unroll
                for (int nt = 0; nt < 8; nt++)
                    mma_f16(acc[mi][nt],
                            a[mi][0], a[mi][1], a[mi][2], a[mi][3],
                            b[nt][0], b[nt][1]);
        }
        __syncthreads();
    }

    // Epilogue: add bias, convert to fp16, store half2
#pragma unroll
    for (int mi = 0; mi < 2; mi++) {
        int r0 = row0 + wm * 32 + mi * 16 + g;
        int r1 = r0 + 8;
#pragma unroll
        for (int nt = 0; nt < 8; nt++) {
            int c = wn * 64 + nt * 8 + 2 * t;
            float bx = __ldg(bias + c), by = __ldg(bias + c + 1);
            if (r0 < n) {
                __half2 v0 = __floats2half2_rn(acc[mi][nt][0] + bx,
                                               acc[mi][nt][1] + by);
                *(__half2*)(out + (size_t)r0 * DIMH + c) = v0;
            }
            if (r1 < n) {
                __half2 v1 = __floats2half2_rn(acc[mi][nt][2] + bx,
                                               acc[mi][nt][3] + by);
                *(__half2*)(out + (size_t)r1 * DIMH + c) = v1;
            }
        }
    }
}

// ---------------------------------------------------------------------------
// Kernel 2 (FUSED): warp per edge.  fp16 Q/K/V loads, fp32 math, REDG out.
// ---------------------------------------------------------------------------
__global__ __launch_bounds__(256)
void fused_edge(const int* __restrict__ ei,
                const float* __restrict__ ebias,
                int E_, float* __restrict__ out_h) {
    int e    = (blockIdx.x * blockDim.x + threadIdx.x) >> 5;
    int lane = threadIdx.x & 31;
    if (e >= E_) return;

    int src = __ldg(ei + e);
    int dst = __ldg(ei + E_ + e);

    __half2 q2[2], k2[2];
    *(uint2*)q2 = *(const uint2*)(g_Q + (size_t)dst * DIMH + lane * 4);
    *(uint2*)k2 = *(const uint2*)(g_K + (size_t)src * DIMH + lane * 4);

    float2 qa = __half22float2(q2[0]), qb = __half22float2(q2[1]);
    float2 ka = __half22float2(k2[0]), kb = __half22float2(k2[1]);

    float p = qa.x * ka.x + qa.y * ka.y + qb.x * kb.x + qb.y * kb.y;
    p += __shfl_xor_sync(0xffffffffu, p, 1);
    p += __shfl_xor_sync(0xffffffffu, p, 2);

    int h = lane >> 2;
    float bias = __ldg(ebias + (size_t)e * NHEADS + h);
    float ex = __expf(p * 0.25f + bias);

    if ((lane & 3) == 0) {
        g_ex[(size_t)e * NHEADS + h] = ex;
        red_add_f32(g_segsum + (size_t)dst * NHEADS + h, ex);
    }

    __half2 v2[2];
    *(uint2*)v2 = *(const uint2*)(g_V + (size_t)src * DIMH + lane * 4);
    float2 va = __half22float2(v2[0]), vb = __half22float2(v2[1]);

    float4 v = make_float4(va.x * ex, va.y * ex, vb.x * ex, vb.y * ex);
    red_add_v4(out_h + (size_t)dst * DIMH + lane * 4, v);
}

// ---------------------------------------------------------------------------
// Kernel 3 (merged finalize): normalize h + write alpha
// ---------------------------------------------------------------------------
__global__ void finalize(const int* __restrict__ ei, int E_, int n,
                         float* __restrict__ out_h,
                         float* __restrict__ out_alpha) {
    int t = blockIdx.x * blockDim.x + threadIdx.x;

    if (t < n * 32) {
        int i = t >> 5;
        int c4 = t & 31;
        float s = g_segsum[(size_t)i * NHEADS + (c4 >> 2)];
        float inv = 1.0f / s;
        float4 v = *(float4*)(out_h + (size_t)i * DIMH + c4 * 4);
        v.x *= inv; v.y *= inv; v.z *= inv; v.w *= inv;
        *(float4*)(out_h + (size_t)i * DIMH + c4 * 4) = v;
    }

    if (t < E_) {
        int dst = __ldg(ei + E_ + t);
        float4 e0 = *(const float4*)(g_ex + (size_t)t * NHEADS);
        float4 e1 = *(const float4*)(g_ex + (size_t)t * NHEADS + 4);
        float4 s0 = *(const float4*)(g_segsum + (size_t)dst * NHEADS);
        float4 s1 = *(const float4*)(g_segsum + (size_t)dst * NHEADS + 4);

        e0.x /= s0.x; e0.y /= s0.y; e0.z /= s0.z; e0.w /= s0.w;
        e1.x /= s1.x; e1.y /= s1.y; e1.z /= s1.z; e1.w /= s1.w;

        *(float4*)(out_alpha + (size_t)t * NHEADS)     = e0;
        *(float4*)(out_alpha + (size_t)t * NHEADS + 4) = e1;
    }
}

// ---------------------------------------------------------------------------
// Launch
// ---------------------------------------------------------------------------
extern "C" void kernel_launch(void* const* d_in, const int* in_sizes, int n_in,
                              void* d_out, int out_size) {
    const float* x     = (const float*)d_in[0];
    const int*   ei    = (const int*)d_in[1];
    const float* ebias = (const float*)d_in[2];
    const float* WQ    = (const float*)d_in[3];
    const float* bQ    = (const float*)d_in[4];
    const float* WK    = (const float*)d_in[5];
    const float* bK    = (const float*)d_in[6];
    const float* WV    = (const float*)d_in[7];
    const float* bV    = (const float*)d_in[8];

    int n = in_sizes[0] / DIMH;     // 50000
    int e = in_sizes[1] / 2;        // 800000

    float* out_h = (float*)d_out;
    float* out_alpha = out_h + (size_t)n * DIMH;

    // 1) QKV projections (fp16 mma.sync m16n8k16) + fused zero-init
    {
        dim3 grid((n + 127) / 128, 3);
        gemm_qkv_mma<<<grid, 256>>>(x, WQ, bQ, WK, bK, WV, bV, n, out_h);
    }
    // 2) fused edge pass
    {
        long long threads = (long long)e * 32;
        int blocks = (int)((threads + 255) / 256);
        fused_edge<<<blocks, 256>>>(ei, ebias, e, out_h);
    }
    // 3) finalize: normalize h + write alpha
    {
        int total = n * 32 > e ? n * 32 : e;
        int blocks = (total + 255) / 256;
        finalize<<<blocks, 256>>>(ei, e, n, out_h, out_alpha);
    }
}

// round 12
// speedup vs baseline: 1.1091x; 1.0005x over previous
#include <cuda_runtime.h>
#include <cuda_bf16.h>
#include <cuda_fp16.h>
#include <cstdint>

#define NMAX 50000
#define EMAX 800000
#define DIMH 128
#define NHEADS 8
#define HEADDIM 16

// ---------------------------------------------------------------------------
// Scratch (fp16 QKV to halve gather traffic; fp32 elsewhere)
// ---------------------------------------------------------------------------
__device__ __half g_Q[(size_t)NMAX * DIMH];
__device__ __half g_K[(size_t)NMAX * DIMH];
__device__ __half g_V[(size_t)NMAX * DIMH];
__device__ float  g_ex[(size_t)EMAX * NHEADS];
__device__ float  g_segsum[(size_t)NMAX * NHEADS];

// ---------------------------------------------------------------------------
// Helpers
// ---------------------------------------------------------------------------
__device__ __forceinline__ void red_add_v4(float* addr, float4 v) {
    asm volatile("red.global.add.v4.f32 [%0], {%1, %2, %3, %4};"
                 :: "l"(addr), "f"(v.x), "f"(v.y), "f"(v.z), "f"(v.w) : "memory");
}
__device__ __forceinline__ void red_add_f32(float* addr, float v) {
    asm volatile("red.global.add.f32 [%0], %1;" :: "l"(addr), "f"(v) : "memory");
}
// fp16 mma m16n8k16: A row-major (4 x half2), B col-major (2 x half2), C fp32
__device__ __forceinline__ void mma_f16(float (&c)[4],
                                        uint32_t a0, uint32_t a1,
                                        uint32_t a2, uint32_t a3,
                                        uint32_t b0, uint32_t b1) {
    asm volatile("mma.sync.aligned.m16n8k16.row.col.f32.f16.f16.f32 "
                 "{%0,%1,%2,%3}, {%4,%5,%6,%7}, {%8,%9}, {%0,%1,%2,%3};"
                 : "+f"(c[0]), "+f"(c[1]), "+f"(c[2]), "+f"(c[3])
                 : "r"(a0), "r"(a1), "r"(a2), "r"(a3), "r"(b0), "r"(b1));
}
__device__ __forceinline__ uint32_t pack_half2(float x, float y) {
    __half2 h = __floats2half2_rn(x, y);
    return *(uint32_t*)&h;
}

// ---------------------------------------------------------------------------
// Kernel 1: fp16 mma.sync GEMM (m16n8k16), SINGLE K-PASS (K=128 in smem).
// 2D warp tiling: 4M x 2N warps -> 32x64 warp tiles.
// Tile layout: [128 rows][68 words] (64 data half2 + 4 pad); 68%32==4 ->
// fragment reads bank = 4g+t+const (all 32 distinct, conflict-free); fill
// writes: 16-lane phase covers banks 0..31 exactly once (conflict-free).
// One __syncthreads total between fill and MMA stream.
// Q-branch CTAs also zero their out_h slice + segsum (fused init).
// ---------------------------------------------------------------------------
#define SPADW 68        // words per row (64 data + 4 pad)
#define TILE_WORDS (128 * SPADW)
#define SMEM_BYTES (2 * TILE_WORDS * 4)

__global__ __launch_bounds__(256)
void gemm_qkv_mma(const float* __restrict__ x,
                  const float* __restrict__ WQ, const float* __restrict__ bQ,
                  const float* __restrict__ WK, const float* __restrict__ bK,
                  const float* __restrict__ WV, const float* __restrict__ bV,
                  int n, float* __restrict__ out_h) {
    const float* W;
    const float* bias;
    __half* out;
    if (blockIdx.y == 0)      { W = WQ; bias = bQ; out = g_Q; }
    else if (blockIdx.y == 1) { W = WK; bias = bK; out = g_K; }
    else                      { W = WV; bias = bV; out = g_V; }

    extern __shared__ uint32_t smem[];
    uint32_t (*As)[SPADW] = (uint32_t(*)[SPADW])smem;
    uint32_t (*Bs)[SPADW] = (uint32_t(*)[SPADW])(smem + TILE_WORDS);

    const int tid  = threadIdx.x;
    const int wid  = tid >> 5;
    const int lane = tid & 31;
    const int g    = lane >> 2;
    const int t    = lane & 3;
    const int row0 = blockIdx.x * 128;
    const int wm   = wid & 3;        // M group: rows [wm*32, wm*32+32)
    const int wn   = wid >> 2;       // N group: cols [wn*64, wn*64+64)

    // --- fused init: Q-branch zeroes out_h rows [row0, row0+128) and segsum
    if (blockIdx.y == 0) {
        float4 z = make_float4(0.f, 0.f, 0.f, 0.f);
#pragma unroll
        for (int i = 0; i < 16; i++) {
            int idx = tid + i * 256;
            int r   = row0 + (idx >> 5);
            if (r < n)
                *(float4*)(out_h + (size_t)r * DIMH + (idx & 31) * 4) = z;
        }
        {
            int r = row0 + (tid >> 1);
            if (r < n)
                *(float4*)(g_segsum + (size_t)r * NHEADS + (tid & 1) * 4) = z;
        }
    }

    // --- fill A (x rows, fp32->fp16, zero-padded) and B (W rows) for full K
    // 128 rows x 32 float4 each = 4096; 16 per thread per tile.
#pragma unroll
    for (int i = 0; i < 16; i++) {
        int u2  = tid + i * 256;         // 0..4095
        int row = u2 >> 5;
        int c   = u2 & 31;               // float4 index within 128-wide row
        int gr  = row0 + row;
        float4 a = make_float4(0.f, 0.f, 0.f, 0.f);
        if (gr < n) a = *(const float4*)(x + (size_t)gr * DIMH + c * 4);
        *(uint2*)&As[row][c * 2] =
            make_uint2(pack_half2(a.x, a.y), pack_half2(a.z, a.w));

        float4 w = *(const float4*)(W + (size_t)row * DIMH + c * 4);
        *(uint2*)&Bs[row][c * 2] =
            make_uint2(pack_half2(w.x, w.y), pack_half2(w.z, w.w));
    }
    __syncthreads();

    float acc[2][8][4];
#pragma unroll
    for (int mi = 0; mi < 2; mi++)
#pragma unroll
        for (int nt = 0; nt < 8; nt++)
#pragma unroll
            for (int j = 0; j < 4; j++) acc[mi][nt][j] = 0.0f;

    // --- uninterrupted MMA stream: 8 k16 steps
#pragma unroll
    for (int ks = 0; ks < 8; ks++) {
        int wk = ks * 8;                 // word offset of this k16 step
        uint32_t a[2][4];
#pragma unroll
        for (int mi = 0; mi < 2; mi++) {
            int r = wm * 32 + mi * 16 + g;
            a[mi][0] = As[r][wk + t];
            a[mi][1] = As[r + 8][wk + t];
            a[mi][2] = As[r][wk + t + 4];
            a[mi][3] = As[r + 8][wk + t + 4];
        }
        uint32_t b[8][2];
#pragma unroll
        for (int nt = 0; nt < 8; nt++) {
            int r = wn * 64 + nt * 8 + g;
            b[nt][0] = Bs[r][wk + t];
            b[nt][1] = Bs[r][wk + t + 4];
        }
#pragma unroll
        for (int mi = 0; mi < 2; mi++)
#pragma unroll
            for (int nt = 0; nt < 8; nt++)
                mma_f16(acc[mi][nt],
                        a[mi][0], a[mi][1], a[mi][2], a[mi][3],
                        b[nt][0], b[nt][1]);
    }

    // Epilogue: add bias, convert to fp16, store half2
#pragma unroll
    for (int mi = 0; mi < 2; mi++) {
        int r0 = row0 + wm * 32 + mi * 16 + g;
        int r1 = r0 + 8;
#pragma unroll
        for (int nt = 0; nt < 8; nt++) {
            int c = wn * 64 + nt * 8 + 2 * t;
            float bx = __ldg(bias + c), by = __ldg(bias + c + 1);
            if (r0 < n) {
                __half2 v0 = __floats2half2_rn(acc[mi][nt][0] + bx,
                                               acc[mi][nt][1] + by);
                *(__half2*)(out + (size_t)r0 * DIMH + c) = v0;
            }
            if (r1 < n) {
                __half2 v1 = __floats2half2_rn(acc[mi][nt][2] + bx,
                                               acc[mi][nt][3] + by);
                *(__half2*)(out + (size_t)r1 * DIMH + c) = v1;
            }
        }
    }
}

// ---------------------------------------------------------------------------
// Kernel 2 (FUSED): warp per edge.  fp16 Q/K/V loads, fp32 math, REDG out.
// ---------------------------------------------------------------------------
__global__ __launch_bounds__(256)
void fused_edge(const int* __restrict__ ei,
                const float* __restrict__ ebias,
                int E_, float* __restrict__ out_h) {
    int e    = (blockIdx.x * blockDim.x + threadIdx.x) >> 5;
    int lane = threadIdx.x & 31;
    if (e >= E_) return;

    int src = __ldg(ei + e);
    int dst = __ldg(ei + E_ + e);

    __half2 q2[2], k2[2];
    *(uint2*)q2 = *(const uint2*)(g_Q + (size_t)dst * DIMH + lane * 4);
    *(uint2*)k2 = *(const uint2*)(g_K + (size_t)src * DIMH + lane * 4);

    float2 qa = __half22float2(q2[0]), qb = __half22float2(q2[1]);
    float2 ka = __half22float2(k2[0]), kb = __half22float2(k2[1]);

    float p = qa.x * ka.x + qa.y * ka.y + qb.x * kb.x + qb.y * kb.y;
    p += __shfl_xor_sync(0xffffffffu, p, 1);
    p += __shfl_xor_sync(0xffffffffu, p, 2);

    int h = lane >> 2;
    float bias = __ldg(ebias + (size_t)e * NHEADS + h);
    float ex = __expf(p * 0.25f + bias);

    if ((lane & 3) == 0) {
        g_ex[(size_t)e * NHEADS + h] = ex;
        red_add_f32(g_segsum + (size_t)dst * NHEADS + h, ex);
    }

    __half2 v2[2];
    *(uint2*)v2 = *(const uint2*)(g_V + (size_t)src * DIMH + lane * 4);
    float2 va = __half22float2(v2[0]), vb = __half22float2(v2[1]);

    float4 v = make_float4(va.x * ex, va.y * ex, vb.x * ex, vb.y * ex);
    red_add_v4(out_h + (size_t)dst * DIMH + lane * 4, v);
}

// ---------------------------------------------------------------------------
// Kernel 3 (merged finalize): normalize h + write alpha
// ---------------------------------------------------------------------------
__global__ void finalize(const int* __restrict__ ei, int E_, int n,
                         float* __restrict__ out_h,
                         float* __restrict__ out_alpha) {
    int t = blockIdx.x * blockDim.x + threadIdx.x;

    if (t < n * 32) {
        int i = t >> 5;
        int c4 = t & 31;
        float s = g_segsum[(size_t)i * NHEADS + (c4 >> 2)];
        float inv = 1.0f / s;
        float4 v = *(float4*)(out_h + (size_t)i * DIMH + c4 * 4);
        v.x *= inv; v.y *= inv; v.z *= inv; v.w *= inv;
        *(float4*)(out_h + (size_t)i * DIMH + c4 * 4) = v;
    }

    if (t < E_) {
        int dst = __ldg(ei + E_ + t);
        float4 e0 = *(const float4*)(g_ex + (size_t)t * NHEADS);
        float4 e1 = *(const float4*)(g_ex + (size_t)t * NHEADS + 4);
        float4 s0 = *(const float4*)(g_segsum + (size_t)dst * NHEADS);
        float4 s1 = *(const float4*)(g_segsum + (size_t)dst * NHEADS + 4);

        e0.x /= s0.x; e0.y /= s0.y; e0.z /= s0.z; e0.w /= s0.w;
        e1.x /= s1.x; e1.y /= s1.y; e1.z /= s1.z; e1.w /= s1.w;

        *(float4*)(out_alpha + (size_t)t * NHEADS)     = e0;
        *(float4*)(out_alpha + (size_t)t * NHEADS + 4) = e1;
    }
}

// ---------------------------------------------------------------------------
// Launch
// ---------------------------------------------------------------------------
extern "C" void kernel_launch(void* const* d_in, const int* in_sizes, int n_in,
                              void* d_out, int out_size) {
    const float* x     = (const float*)d_in[0];
    const int*   ei    = (const int*)d_in[1];
    const float* ebias = (const float*)d_in[2];
    const float* WQ    = (const float*)d_in[3];
    const float* bQ    = (const float*)d_in[4];
    const float* WK    = (const float*)d_in[5];
    const float* bK    = (const float*)d_in[6];
    const float* WV    = (const float*)d_in[7];
    const float* bV    = (const float*)d_in[8];

    int n = in_sizes[0] / DIMH;     // 50000
    int e = in_sizes[1] / 2;        // 800000

    float* out_h = (float*)d_out;
    float* out_alpha = out_h + (size_t)n * DIMH;

    // 1) QKV projections (fp16 mma.sync, single K-pass) + fused zero-init
    {
        cudaFuncSetAttribute(gemm_qkv_mma,
                             cudaFuncAttributeMaxDynamicSharedMemorySize,
                             SMEM_BYTES);
        dim3 grid((n + 127) / 128, 3);
        gemm_qkv_mma<<<grid, 256, SMEM_BYTES>>>(
            x, WQ, bQ, WK, bK, WV, bV, n, out_h);
    }
    // 2) fused edge pass
    {
        long long threads = (long long)e * 32;
        int blocks = (int)((threads + 255) / 256);
        fused_edge<<<blocks, 256>>>(ei, ebias, e, out_h);
    }
    // 3) finalize: normalize h + write alpha
    {
        int total = n * 32 > e ? n * 32 : e;
        int blocks = (total + 255) / 256;
        finalize<<<blocks, 256>>>(ei, e, n, out_h, out_alpha);
    }
}

// round 13
// speedup vs baseline: 1.1207x; 1.0105x over previous
#include <cuda_runtime.h>
#include <cuda_bf16.h>
#include <cuda_fp16.h>
#include <cstdint>

#define NMAX 50000
#define EMAX 800000
#define DIMH 128
#define NHEADS 8
#define HEADDIM 16

// ---------------------------------------------------------------------------
// Scratch (fp16 QKV to halve gather traffic; fp32 elsewhere)
// ---------------------------------------------------------------------------
__device__ __half g_Q[(size_t)NMAX * DIMH];
__device__ __half g_K[(size_t)NMAX * DIMH];
__device__ __half g_V[(size_t)NMAX * DIMH];
__device__ float  g_ex[(size_t)EMAX * NHEADS];
__device__ float  g_segsum[(size_t)NMAX * NHEADS];

// ---------------------------------------------------------------------------
// Helpers
// ---------------------------------------------------------------------------
__device__ __forceinline__ void red_add_v4(float* addr, float4 v) {
    asm volatile("red.global.add.v4.f32 [%0], {%1, %2, %3, %4};"
                 :: "l"(addr), "f"(v.x), "f"(v.y), "f"(v.z), "f"(v.w) : "memory");
}
__device__ __forceinline__ void red_add_f32(float* addr, float v) {
    asm volatile("red.global.add.f32 [%0], %1;" :: "l"(addr), "f"(v) : "memory");
}
// fp16 mma m16n8k16: A row-major (4 x half2), B col-major (2 x half2), C fp32
__device__ __forceinline__ void mma_f16(float (&c)[4],
                                        uint32_t a0, uint32_t a1,
                                        uint32_t a2, uint32_t a3,
                                        uint32_t b0, uint32_t b1) {
    asm volatile("mma.sync.aligned.m16n8k16.row.col.f32.f16.f16.f32 "
                 "{%0,%1,%2,%3}, {%4,%5,%6,%7}, {%8,%9}, {%0,%1,%2,%3};"
                 : "+f"(c[0]), "+f"(c[1]), "+f"(c[2]), "+f"(c[3])
                 : "r"(a0), "r"(a1), "r"(a2), "r"(a3), "r"(b0), "r"(b1));
}
__device__ __forceinline__ uint32_t pack_half2(float x, float y) {
    __half2 h = __floats2half2_rn(x, y);
    return *(uint32_t*)&h;
}

// ---------------------------------------------------------------------------
// Kernel 1: fp16 mma.sync GEMM (m16n8k16), PERSISTENT-W.
// grid (196, 3): each CTA fills its W tile ONCE, then loops over M-tiles
// (ti = bx, bx+196) refilling only the A (x) tile.  392 tile-slots cover the
// 391 tiles; 588 CTAs = exactly 2 waves at 2 CTAs/SM.
// Tile layout: [128 rows][68 words] (64 data half2 + 4 pad); 68%32==4 ->
// fragment reads bank = 4g+t+const (all 32 distinct, conflict-free); fill
// writes: 16-lane phase covers banks 0..31 exactly once (conflict-free).
// Q-branch CTAs also zero their out_h slice + segsum (fused init).
// ---------------------------------------------------------------------------
#define SPADW 68        // words per row (64 data + 4 pad)
#define TILE_WORDS (128 * SPADW)
#define SMEM_BYTES (2 * TILE_WORDS * 4)
#define GRID_X 196

__global__ __launch_bounds__(256)
void gemm_qkv_mma(const float* __restrict__ x,
                  const float* __restrict__ WQ, const float* __restrict__ bQ,
                  const float* __restrict__ WK, const float* __restrict__ bK,
                  const float* __restrict__ WV, const float* __restrict__ bV,
                  int n, float* __restrict__ out_h) {
    const float* W;
    const float* bias;
    __half* out;
    if (blockIdx.y == 0)      { W = WQ; bias = bQ; out = g_Q; }
    else if (blockIdx.y == 1) { W = WK; bias = bK; out = g_K; }
    else                      { W = WV; bias = bV; out = g_V; }

    extern __shared__ uint32_t smem[];
    uint32_t (*Bs)[SPADW] = (uint32_t(*)[SPADW])smem;
    uint32_t (*As)[SPADW] = (uint32_t(*)[SPADW])(smem + TILE_WORDS);

    const int tid  = threadIdx.x;
    const int wid  = tid >> 5;
    const int lane = tid & 31;
    const int g    = lane >> 2;
    const int t    = lane & 3;
    const int wm   = wid & 3;        // M group: rows [wm*32, wm*32+32)
    const int wn   = wid >> 2;       // N group: cols [wn*64, wn*64+64)
    const int ntiles = (n + 127) >> 7;

    // --- fill W tile ONCE (128 rows x 32 float4 = 4096; 16 per thread)
#pragma unroll
    for (int i = 0; i < 16; i++) {
        int u2  = tid + i * 256;
        int row = u2 >> 5;
        int c   = u2 & 31;
        float4 w = *(const float4*)(W + (size_t)row * DIMH + c * 4);
        *(uint2*)&Bs[row][c * 2] =
            make_uint2(pack_half2(w.x, w.y), pack_half2(w.z, w.w));
    }

    for (int ti = blockIdx.x; ti < ntiles; ti += GRID_X) {
        const int row0 = ti * 128;

        // --- fused init: Q-branch zeroes out_h rows [row0,row0+128) + segsum
        if (blockIdx.y == 0) {
            float4 z = make_float4(0.f, 0.f, 0.f, 0.f);
#pragma unroll
            for (int i = 0; i < 16; i++) {
                int idx = tid + i * 256;
                int r   = row0 + (idx >> 5);
                if (r < n)
                    *(float4*)(out_h + (size_t)r * DIMH + (idx & 31) * 4) = z;
            }
            {
                int r = row0 + (tid >> 1);
                if (r < n)
                    *(float4*)(g_segsum + (size_t)r * NHEADS + (tid & 1) * 4) = z;
            }
        }

        // --- fill A tile (x rows, fp32->fp16, zero-padded)
#pragma unroll
        for (int i = 0; i < 16; i++) {
            int u2  = tid + i * 256;
            int row = u2 >> 5;
            int c   = u2 & 31;
            int gr  = row0 + row;
            float4 a = make_float4(0.f, 0.f, 0.f, 0.f);
            if (gr < n) a = *(const float4*)(x + (size_t)gr * DIMH + c * 4);
            *(uint2*)&As[row][c * 2] =
                make_uint2(pack_half2(a.x, a.y), pack_half2(a.z, a.w));
        }
        __syncthreads();

        float acc[2][8][4];
#pragma unroll
        for (int mi = 0; mi < 2; mi++)
#pragma unroll
            for (int nt = 0; nt < 8; nt++)
#pragma unroll
                for (int j = 0; j < 4; j++) acc[mi][nt][j] = 0.0f;

        // --- MMA stream: 8 k16 steps
#pragma unroll
        for (int ks = 0; ks < 8; ks++) {
            int wk = ks * 8;
            uint32_t a[2][4];
#pragma unroll
            for (int mi = 0; mi < 2; mi++) {
                int r = wm * 32 + mi * 16 + g;
                a[mi][0] = As[r][wk + t];
                a[mi][1] = As[r + 8][wk + t];
                a[mi][2] = As[r][wk + t + 4];
                a[mi][3] = As[r + 8][wk + t + 4];
            }
            uint32_t b[8][2];
#pragma unroll
            for (int nt = 0; nt < 8; nt++) {
                int r = wn * 64 + nt * 8 + g;
                b[nt][0] = Bs[r][wk + t];
                b[nt][1] = Bs[r][wk + t + 4];
            }
#pragma unroll
            for (int mi = 0; mi < 2; mi++)
#pragma unroll
                for (int nt = 0; nt < 8; nt++)
                    mma_f16(acc[mi][nt],
                            a[mi][0], a[mi][1], a[mi][2], a[mi][3],
                            b[nt][0], b[nt][1]);
        }

        // Epilogue: add bias, convert to fp16, store half2
#pragma unroll
        for (int mi = 0; mi < 2; mi++) {
            int r0 = row0 + wm * 32 + mi * 16 + g;
            int r1 = r0 + 8;
#pragma unroll
            for (int nt = 0; nt < 8; nt++) {
                int c = wn * 64 + nt * 8 + 2 * t;
                float bx = __ldg(bias + c), by = __ldg(bias + c + 1);
                if (r0 < n) {
                    __half2 v0 = __floats2half2_rn(acc[mi][nt][0] + bx,
                                                   acc[mi][nt][1] + by);
                    *(__half2*)(out + (size_t)r0 * DIMH + c) = v0;
                }
                if (r1 < n) {
                    __half2 v1 = __floats2half2_rn(acc[mi][nt][2] + bx,
                                                   acc[mi][nt][3] + by);
                    *(__half2*)(out + (size_t)r1 * DIMH + c) = v1;
                }
            }
        }
        __syncthreads();   // all reads of As done before next tile's fill
    }
}

// ---------------------------------------------------------------------------
// Kernel 2 (FUSED): warp per edge.  fp16 Q/K/V loads, fp32 math, REDG out.
// ---------------------------------------------------------------------------
__global__ __launch_bounds__(256)
void fused_edge(const int* __restrict__ ei,
                const float* __restrict__ ebias,
                int E_, float* __restrict__ out_h) {
    int e    = (blockIdx.x * blockDim.x + threadIdx.x) >> 5;
    int lane = threadIdx.x & 31;
    if (e >= E_) return;

    int src = __ldg(ei + e);
    int dst = __ldg(ei + E_ + e);

    __half2 q2[2], k2[2];
    *(uint2*)q2 = *(const uint2*)(g_Q + (size_t)dst * DIMH + lane * 4);
    *(uint2*)k2 = *(const uint2*)(g_K + (size_t)src * DIMH + lane * 4);

    float2 qa = __half22float2(q2[0]), qb = __half22float2(q2[1]);
    float2 ka = __half22float2(k2[0]), kb = __half22float2(k2[1]);

    float p = qa.x * ka.x + qa.y * ka.y + qb.x * kb.x + qb.y * kb.y;
    p += __shfl_xor_sync(0xffffffffu, p, 1);
    p += __shfl_xor_sync(0xffffffffu, p, 2);

    int h = lane >> 2;
    float bias = __ldg(ebias + (size_t)e * NHEADS + h);
    float ex = __expf(p * 0.25f + bias);

    if ((lane & 3) == 0) {
        g_ex[(size_t)e * NHEADS + h] = ex;
        red_add_f32(g_segsum + (size_t)dst * NHEADS + h, ex);
    }

    __half2 v2[2];
    *(uint2*)v2 = *(const uint2*)(g_V + (size_t)src * DIMH + lane * 4);
    float2 va = __half22float2(v2[0]), vb = __half22float2(v2[1]);

    float4 v = make_float4(va.x * ex, va.y * ex, vb.x * ex, vb.y * ex);
    red_add_v4(out_h + (size_t)dst * DIMH + lane * 4, v);
}

// ---------------------------------------------------------------------------
// Kernel 3 (merged finalize): normalize h + write alpha
// ---------------------------------------------------------------------------
__global__ void finalize(const int* __restrict__ ei, int E_, int n,
                         float* __restrict__ out_h,
                         float* __restrict__ out_alpha) {
    int t = blockIdx.x * blockDim.x + threadIdx.x;

    if (t < n * 32) {
        int i = t >> 5;
        int c4 = t & 31;
        float s = g_segsum[(size_t)i * NHEADS + (c4 >> 2)];
        float inv = 1.0f / s;
        float4 v = *(float4*)(out_h + (size_t)i * DIMH + c4 * 4);
        v.x *= inv; v.y *= inv; v.z *= inv; v.w *= inv;
        *(float4*)(out_h + (size_t)i * DIMH + c4 * 4) = v;
    }

    if (t < E_) {
        int dst = __ldg(ei + E_ + t);
        float4 e0 = *(const float4*)(g_ex + (size_t)t * NHEADS);
        float4 e1 = *(const float4*)(g_ex + (size_t)t * NHEADS + 4);
        float4 s0 = *(const float4*)(g_segsum + (size_t)dst * NHEADS);
        float4 s1 = *(const float4*)(g_segsum + (size_t)dst * NHEADS + 4);

        e0.x /= s0.x; e0.y /= s0.y; e0.z /= s0.z; e0.w /= s0.w;
        e1.x /= s1.x; e1.y /= s1.y; e1.z /= s1.z; e1.w /= s1.w;

        *(float4*)(out_alpha + (size_t)t * NHEADS)     = e0;
        *(float4*)(out_alpha + (size_t)t * NHEADS + 4) = e1;
    }
}

// ---------------------------------------------------------------------------
// Launch
// ---------------------------------------------------------------------------
extern "C" void kernel_launch(void* const* d_in, const int* in_sizes, int n_in,
                              void* d_out, int out_size) {
    const float* x     = (const float*)d_in[0];
    const int*   ei    = (const int*)d_in[1];
    const float* ebias = (const float*)d_in[2];
    const float* WQ    = (const float*)d_in[3];
    const float* bQ    = (const float*)d_in[4];
    const float* WK    = (const float*)d_in[5];
    const float* bK    = (const float*)d_in[6];
    const float* WV    = (const float*)d_in[7];
    const float* bV    = (const float*)d_in[8];

    int n = in_sizes[0] / DIMH;     // 50000
    int e = in_sizes[1] / 2;        // 800000

    float* out_h = (float*)d_out;
    float* out_alpha = out_h + (size_t)n * DIMH;

    // 1) QKV projections (fp16 mma.sync, persistent-W) + fused zero-init
    {
        cudaFuncSetAttribute(gemm_qkv_mma,
                             cudaFuncAttributeMaxDynamicSharedMemorySize,
                             SMEM_BYTES);
        dim3 grid(GRID_X, 3);
        gemm_qkv_mma<<<grid, 256, SMEM_BYTES>>>(
            x, WQ, bQ, WK, bK, WV, bV, n, out_h);
    }
    // 2) fused edge pass
    {
        long long threads = (long long)e * 32;
        int blocks = (int)((threads + 255) / 256);
        fused_edge<<<blocks, 256>>>(ei, ebias, e, out_h);
    }
    // 3) finalize: normalize h + write alpha
    {
        int total = n * 32 > e ? n * 32 : e;
        int blocks = (total + 255) / 256;
        finalize<<<blocks, 256>>>(ei, e, n, out_h, out_alpha);
    }
}

// round 14
// speedup vs baseline: 1.1290x; 1.0074x over previous
#include <cuda_runtime.h>
#include <cuda_bf16.h>
#include <cuda_fp16.h>
#include <cstdint>

#define NMAX 50000
#define EMAX 800000
#define DIMH 128
#define NHEADS 8
#define HEADDIM 16

// ---------------------------------------------------------------------------
// Scratch (fp16 QKV to halve gather traffic; fp32 elsewhere)
// ---------------------------------------------------------------------------
__device__ __half g_Q[(size_t)NMAX * DIMH];
__device__ __half g_K[(size_t)NMAX * DIMH];
__device__ __half g_V[(size_t)NMAX * DIMH];
__device__ float  g_ex[(size_t)EMAX * NHEADS];
__device__ float  g_segsum[(size_t)NMAX * NHEADS];

// ---------------------------------------------------------------------------
// Helpers
// ---------------------------------------------------------------------------
__device__ __forceinline__ void red_add_v4(float* addr, float4 v) {
    asm volatile("red.global.add.v4.f32 [%0], {%1, %2, %3, %4};"
                 :: "l"(addr), "f"(v.x), "f"(v.y), "f"(v.z), "f"(v.w) : "memory");
}
__device__ __forceinline__ void red_add_f32(float* addr, float v) {
    asm volatile("red.global.add.f32 [%0], %1;" :: "l"(addr), "f"(v) : "memory");
}
// fp16 mma m16n8k16: A row-major (4 x half2), B col-major (2 x half2), C fp32
__device__ __forceinline__ void mma_f16(float (&c)[4],
                                        uint32_t a0, uint32_t a1,
                                        uint32_t a2, uint32_t a3,
                                        uint32_t b0, uint32_t b1) {
    asm volatile("mma.sync.aligned.m16n8k16.row.col.f32.f16.f16.f32 "
                 "{%0,%1,%2,%3}, {%4,%5,%6,%7}, {%8,%9}, {%0,%1,%2,%3};"
                 : "+f"(c[0]), "+f"(c[1]), "+f"(c[2]), "+f"(c[3])
                 : "r"(a0), "r"(a1), "r"(a2), "r"(a3), "r"(b0), "r"(b1));
}
__device__ __forceinline__ uint32_t pack_half2(float x, float y) {
    __half2 h = __floats2half2_rn(x, y);
    return *(uint32_t*)&h;
}

// ---------------------------------------------------------------------------
// Kernel 1: fp16 mma.sync GEMM (m16n8k16), PERSISTENT-W, reg-capped.
// __launch_bounds__(256, 2) caps regs at 128 -> 2 CTAs/SM (occupancy fix
// for R13's 154-reg / 1-CTA regression).
// grid (196, 3): each CTA fills its W tile ONCE, loops over M-tiles,
// refilling only the A (x) tile.
// Tile layout: [128 rows][68 words]; conflict-free reads (bank 4g+t) and
// fills (16-lane phase covers banks 0..31 once).
// Q-branch CTAs also zero their out_h slice + segsum (fused init).
// ---------------------------------------------------------------------------
#define SPADW 68        // words per row (64 data + 4 pad)
#define TILE_WORDS (128 * SPADW)
#define SMEM_BYTES (2 * TILE_WORDS * 4)
#define GRID_X 196

__global__ __launch_bounds__(256, 2)
void gemm_qkv_mma(const float* __restrict__ x,
                  const float* __restrict__ WQ, const float* __restrict__ bQ,
                  const float* __restrict__ WK, const float* __restrict__ bK,
                  const float* __restrict__ WV, const float* __restrict__ bV,
                  int n, float* __restrict__ out_h) {
    const float* W;
    const float* bias;
    __half* out;
    if (blockIdx.y == 0)      { W = WQ; bias = bQ; out = g_Q; }
    else if (blockIdx.y == 1) { W = WK; bias = bK; out = g_K; }
    else                      { W = WV; bias = bV; out = g_V; }

    extern __shared__ uint32_t smem[];
    uint32_t (*Bs)[SPADW] = (uint32_t(*)[SPADW])smem;
    uint32_t (*As)[SPADW] = (uint32_t(*)[SPADW])(smem + TILE_WORDS);

    const int tid  = threadIdx.x;
    const int wid  = tid >> 5;
    const int lane = tid & 31;
    const int g    = lane >> 2;
    const int t    = lane & 3;
    const int wm   = wid & 3;        // M group: rows [wm*32, wm*32+32)
    const int wn   = wid >> 2;       // N group: cols [wn*64, wn*64+64)
    const int ntiles = (n + 127) >> 7;

    // --- fill W tile ONCE (128 rows x 32 float4 = 4096; 16 per thread)
#pragma unroll
    for (int i = 0; i < 16; i++) {
        int u2  = tid + i * 256;
        int row = u2 >> 5;
        int c   = u2 & 31;
        float4 w = *(const float4*)(W + (size_t)row * DIMH + c * 4);
        *(uint2*)&Bs[row][c * 2] =
            make_uint2(pack_half2(w.x, w.y), pack_half2(w.z, w.w));
    }

    for (int ti = blockIdx.x; ti < ntiles; ti += GRID_X) {
        const int row0 = ti * 128;

        // --- fused init: Q-branch zeroes out_h rows [row0,row0+128) + segsum
        if (blockIdx.y == 0) {
            float4 z = make_float4(0.f, 0.f, 0.f, 0.f);
#pragma unroll
            for (int i = 0; i < 16; i++) {
                int idx = tid + i * 256;
                int r   = row0 + (idx >> 5);
                if (r < n)
                    *(float4*)(out_h + (size_t)r * DIMH + (idx & 31) * 4) = z;
            }
            {
                int r = row0 + (tid >> 1);
                if (r < n)
                    *(float4*)(g_segsum + (size_t)r * NHEADS + (tid & 1) * 4) = z;
            }
        }

        // --- fill A tile (x rows, fp32->fp16, zero-padded)
#pragma unroll
        for (int i = 0; i < 16; i++) {
            int u2  = tid + i * 256;
            int row = u2 >> 5;
            int c   = u2 & 31;
            int gr  = row0 + row;
            float4 a = make_float4(0.f, 0.f, 0.f, 0.f);
            if (gr < n) a = *(const float4*)(x + (size_t)gr * DIMH + c * 4);
            *(uint2*)&As[row][c * 2] =
                make_uint2(pack_half2(a.x, a.y), pack_half2(a.z, a.w));
        }
        __syncthreads();

        float acc[2][8][4];
#pragma unroll
        for (int mi = 0; mi < 2; mi++)
#pragma unroll
            for (int nt = 0; nt < 8; nt++)
#pragma unroll
                for (int j = 0; j < 4; j++) acc[mi][nt][j] = 0.0f;

        // --- MMA stream: 8 k16 steps
#pragma unroll
        for (int ks = 0; ks < 8; ks++) {
            int wk = ks * 8;
            uint32_t a[2][4];
#pragma unroll
            for (int mi = 0; mi < 2; mi++) {
                int r = wm * 32 + mi * 16 + g;
                a[mi][0] = As[r][wk + t];
                a[mi][1] = As[r + 8][wk + t];
                a[mi][2] = As[r][wk + t + 4];
                a[mi][3] = As[r + 8][wk + t + 4];
            }
            uint32_t b[8][2];
#pragma unroll
            for (int nt = 0; nt < 8; nt++) {
                int r = wn * 64 + nt * 8 + g;
                b[nt][0] = Bs[r][wk + t];
                b[nt][1] = Bs[r][wk + t + 4];
            }
#pragma unroll
            for (int mi = 0; mi < 2; mi++)
#pragma unroll
                for (int nt = 0; nt < 8; nt++)
                    mma_f16(acc[mi][nt],
                            a[mi][0], a[mi][1], a[mi][2], a[mi][3],
                            b[nt][0], b[nt][1]);
        }

        // Epilogue: add bias, convert to fp16, store half2
#pragma unroll
        for (int mi = 0; mi < 2; mi++) {
            int r0 = row0 + wm * 32 + mi * 16 + g;
            int r1 = r0 + 8;
#pragma unroll
            for (int nt = 0; nt < 8; nt++) {
                int c = wn * 64 + nt * 8 + 2 * t;
                float bx = __ldg(bias + c), by = __ldg(bias + c + 1);
                if (r0 < n) {
                    __half2 v0 = __floats2half2_rn(acc[mi][nt][0] + bx,
                                                   acc[mi][nt][1] + by);
                    *(__half2*)(out + (size_t)r0 * DIMH + c) = v0;
                }
                if (r1 < n) {
                    __half2 v1 = __floats2half2_rn(acc[mi][nt][2] + bx,
                                                   acc[mi][nt][3] + by);
                    *(__half2*)(out + (size_t)r1 * DIMH + c) = v1;
                }
            }
        }
        __syncthreads();   // all reads of As done before next tile's fill
    }
}

// ---------------------------------------------------------------------------
// Kernel 2 (FUSED): warp per edge.  fp16 Q/K/V loads, fp32 math, REDG out.
// ---------------------------------------------------------------------------
__global__ __launch_bounds__(256)
void fused_edge(const int* __restrict__ ei,
                const float* __restrict__ ebias,
                int E_, float* __restrict__ out_h) {
    int e    = (blockIdx.x * blockDim.x + threadIdx.x) >> 5;
    int lane = threadIdx.x & 31;
    if (e >= E_) return;

    int src = __ldg(ei + e);
    int dst = __ldg(ei + E_ + e);

    __half2 q2[2], k2[2];
    *(uint2*)q2 = *(const uint2*)(g_Q + (size_t)dst * DIMH + lane * 4);
    *(uint2*)k2 = *(const uint2*)(g_K + (size_t)src * DIMH + lane * 4);

    float2 qa = __half22float2(q2[0]), qb = __half22float2(q2[1]);
    float2 ka = __half22float2(k2[0]), kb = __half22float2(k2[1]);

    float p = qa.x * ka.x + qa.y * ka.y + qb.x * kb.x + qb.y * kb.y;
    p += __shfl_xor_sync(0xffffffffu, p, 1);
    p += __shfl_xor_sync(0xffffffffu, p, 2);

    int h = lane >> 2;
    float bias = __ldg(ebias + (size_t)e * NHEADS + h);
    float ex = __expf(p * 0.25f + bias);

    if ((lane & 3) == 0) {
        g_ex[(size_t)e * NHEADS + h] = ex;
        red_add_f32(g_segsum + (size_t)dst * NHEADS + h, ex);
    }

    __half2 v2[2];
    *(uint2*)v2 = *(const uint2*)(g_V + (size_t)src * DIMH + lane * 4);
    float2 va = __half22float2(v2[0]), vb = __half22float2(v2[1]);

    float4 v = make_float4(va.x * ex, va.y * ex, vb.x * ex, vb.y * ex);
    red_add_v4(out_h + (size_t)dst * DIMH + lane * 4, v);
}

// ---------------------------------------------------------------------------
// Kernel 3 (merged finalize): normalize h + write alpha
// ---------------------------------------------------------------------------
__global__ void finalize(const int* __restrict__ ei, int E_, int n,
                         float* __restrict__ out_h,
                         float* __restrict__ out_alpha) {
    int t = blockIdx.x * blockDim.x + threadIdx.x;

    if (t < n * 32) {
        int i = t >> 5;
        int c4 = t & 31;
        float s = g_segsum[(size_t)i * NHEADS + (c4 >> 2)];
        float inv = 1.0f / s;
        float4 v = *(float4*)(out_h + (size_t)i * DIMH + c4 * 4);
        v.x *= inv; v.y *= inv; v.z *= inv; v.w *= inv;
        *(float4*)(out_h + (size_t)i * DIMH + c4 * 4) = v;
    }

    if (t < E_) {
        int dst = __ldg(ei + E_ + t);
        float4 e0 = *(const float4*)(g_ex + (size_t)t * NHEADS);
        float4 e1 = *(const float4*)(g_ex + (size_t)t * NHEADS + 4);
        float4 s0 = *(const float4*)(g_segsum + (size_t)dst * NHEADS);
        float4 s1 = *(const float4*)(g_segsum + (size_t)dst * NHEADS + 4);

        e0.x /= s0.x; e0.y /= s0.y; e0.z /= s0.z; e0.w /= s0.w;
        e1.x /= s1.x; e1.y /= s1.y; e1.z /= s1.z; e1.w /= s1.w;

        *(float4*)(out_alpha + (size_t)t * NHEADS)     = e0;
        *(float4*)(out_alpha + (size_t)t * NHEADS + 4) = e1;
    }
}

// ---------------------------------------------------------------------------
// Launch
// ---------------------------------------------------------------------------
extern "C" void kernel_launch(void* const* d_in, const int* in_sizes, int n_in,
                              void* d_out, int out_size) {
    const float* x     = (const float*)d_in[0];
    const int*   ei    = (const int*)d_in[1];
    const float* ebias = (const float*)d_in[2];
    const float* WQ    = (const float*)d_in[3];
    const float* bQ    = (const float*)d_in[4];
    const float* WK    = (const float*)d_in[5];
    const float* bK    = (const float*)d_in[6];
    const float* WV    = (const float*)d_in[7];
    const float* bV    = (const float*)d_in[8];

    int n = in_sizes[0] / DIMH;     // 50000
    int e = in_sizes[1] / 2;        // 800000

    float* out_h = (float*)d_out;
    float* out_alpha = out_h + (size_t)n * DIMH;

    // 1) QKV projections (fp16 mma.sync, persistent-W, 2 CTA/SM) + fused init
    {
        cudaFuncSetAttribute(gemm_qkv_mma,
                             cudaFuncAttributeMaxDynamicSharedMemorySize,
                             SMEM_BYTES);
        dim3 grid(GRID_X, 3);
        gemm_qkv_mma<<<grid, 256, SMEM_BYTES>>>(
            x, WQ, bQ, WK, bK, WV, bV, n, out_h);
    }
    // 2) fused edge pass
    {
        long long threads = (long long)e * 32;
        int blocks = (int)((threads + 255) / 256);
        fused_edge<<<blocks, 256>>>(ei, ebias, e, out_h);
    }
    // 3) finalize: normalize h + write alpha
    {
        int total = n * 32 > e ? n * 32 : e;
        int blocks = (total + 255) / 256;
        finalize<<<blocks, 256>>>(ei, e, n, out_h, out_alpha);
    }
}

// round 15
// speedup vs baseline: 1.1304x; 1.0012x over previous
#include <cuda_runtime.h>
#include <cuda_bf16.h>
#include <cuda_fp16.h>
#include <cstdint>

#define NMAX 50000
#define EMAX 800000
#define DIMH 128
#define NHEADS 8
#define HEADDIM 16

// ---------------------------------------------------------------------------
// Scratch (fp16 QKV to halve gather traffic; fp32 elsewhere)
// ---------------------------------------------------------------------------
__device__ __half g_Q[(size_t)NMAX * DIMH];
__device__ __half g_K[(size_t)NMAX * DIMH];
__device__ __half g_V[(size_t)NMAX * DIMH];
__device__ float  g_ex[(size_t)EMAX * NHEADS];
__device__ float  g_segsum[(size_t)NMAX * NHEADS];

// ---------------------------------------------------------------------------
// Helpers
// ---------------------------------------------------------------------------
__device__ __forceinline__ void red_add_v4(float* addr, float4 v) {
    asm volatile("red.global.add.v4.f32 [%0], {%1, %2, %3, %4};"
                 :: "l"(addr), "f"(v.x), "f"(v.y), "f"(v.z), "f"(v.w) : "memory");
}
__device__ __forceinline__ void red_add_f32(float* addr, float v) {
    asm volatile("red.global.add.f32 [%0], %1;" :: "l"(addr), "f"(v) : "memory");
}
// fp16 mma m16n8k16: A row-major (4 x half2), B col-major (2 x half2), C fp32
__device__ __forceinline__ void mma_f16(float (&c)[4],
                                        uint32_t a0, uint32_t a1,
                                        uint32_t a2, uint32_t a3,
                                        uint32_t b0, uint32_t b1) {
    asm volatile("mma.sync.aligned.m16n8k16.row.col.f32.f16.f16.f32 "
                 "{%0,%1,%2,%3}, {%4,%5,%6,%7}, {%8,%9}, {%0,%1,%2,%3};"
                 : "+f"(c[0]), "+f"(c[1]), "+f"(c[2]), "+f"(c[3])
                 : "r"(a0), "r"(a1), "r"(a2), "r"(a3), "r"(b0), "r"(b1));
}
__device__ __forceinline__ uint32_t pack_half2(float x, float y) {
    __half2 h = __floats2half2_rn(x, y);
    return *(uint32_t*)&h;
}

// ---------------------------------------------------------------------------
// Kernel 1: fp16 mma.sync GEMM (m16n8k16), SHARED-A / 3-BRANCH.
// grid (148): 1 CTA/SM (136 KB smem).  Each CTA fills the three W tiles
// ONCE, then loops over M-tiles: fill the x tile ONCE, and run Q,K,V
// MMA+epilogue sequentially against it (x read 1x instead of 3x,
// fp32->fp16 conversion done once instead of 3x).
// Tile layout: [128 rows][68 words]; conflict-free reads (bank 4g+t) and
// fills (16-lane phase covers banks 0..31 once).
// Each tile-slot also zeroes its out_h slice + segsum (fused init).
// ---------------------------------------------------------------------------
#define SPADW 68        // words per row (64 data + 4 pad)
#define TILE_WORDS (128 * SPADW)
#define SMEM_BYTES (4 * TILE_WORDS * 4)   // 3 W tiles + 1 A tile = 136 KB
#define GRID_X 148

__global__ __launch_bounds__(256)
void gemm_qkv_mma(const float* __restrict__ x,
                  const float* __restrict__ WQ, const float* __restrict__ bQ,
                  const float* __restrict__ WK, const float* __restrict__ bK,
                  const float* __restrict__ WV, const float* __restrict__ bV,
                  int n, float* __restrict__ out_h) {
    extern __shared__ uint32_t smem[];
    uint32_t (*As)[SPADW] = (uint32_t(*)[SPADW])(smem + 3 * TILE_WORDS);

    const int tid  = threadIdx.x;
    const int wid  = tid >> 5;
    const int lane = tid & 31;
    const int g    = lane >> 2;
    const int t    = lane & 3;
    const int wm   = wid & 3;        // M group: rows [wm*32, wm*32+32)
    const int wn   = wid >> 2;       // N group: cols [wn*64, wn*64+64)
    const int ntiles = (n + 127) >> 7;

    // --- fill the three W tiles ONCE
#pragma unroll 1
    for (int br = 0; br < 3; br++) {
        const float* W = (br == 0) ? WQ : (br == 1) ? WK : WV;
        uint32_t (*Bs)[SPADW] = (uint32_t(*)[SPADW])(smem + br * TILE_WORDS);
#pragma unroll
        for (int i = 0; i < 16; i++) {
            int u2  = tid + i * 256;
            int row = u2 >> 5;
            int c   = u2 & 31;
            float4 w = *(const float4*)(W + (size_t)row * DIMH + c * 4);
            *(uint2*)&Bs[row][c * 2] =
                make_uint2(pack_half2(w.x, w.y), pack_half2(w.z, w.w));
        }
    }

#pragma unroll 1
    for (int ti = blockIdx.x; ti < ntiles; ti += GRID_X) {
        const int row0 = ti * 128;

        // --- fused init: zero out_h rows [row0,row0+128) + segsum slice
        {
            float4 z = make_float4(0.f, 0.f, 0.f, 0.f);
#pragma unroll
            for (int i = 0; i < 16; i++) {
                int idx = tid + i * 256;
                int r   = row0 + (idx >> 5);
                if (r < n)
                    *(float4*)(out_h + (size_t)r * DIMH + (idx & 31) * 4) = z;
            }
            {
                int r = row0 + (tid >> 1);
                if (r < n)
                    *(float4*)(g_segsum + (size_t)r * NHEADS + (tid & 1) * 4) = z;
            }
        }

        // --- fill A tile (x rows, fp32->fp16, zero-padded) ONCE per tile
#pragma unroll
        for (int i = 0; i < 16; i++) {
            int u2  = tid + i * 256;
            int row = u2 >> 5;
            int c   = u2 & 31;
            int gr  = row0 + row;
            float4 a = make_float4(0.f, 0.f, 0.f, 0.f);
            if (gr < n) a = *(const float4*)(x + (size_t)gr * DIMH + c * 4);
            *(uint2*)&As[row][c * 2] =
                make_uint2(pack_half2(a.x, a.y), pack_half2(a.z, a.w));
        }
        __syncthreads();

        // --- three branches against the same A tile
#pragma unroll 1
        for (int br = 0; br < 3; br++) {
            const float* bias = (br == 0) ? bQ : (br == 1) ? bK : bV;
            __half* out       = (br == 0) ? g_Q : (br == 1) ? g_K : g_V;
            uint32_t (*Bs)[SPADW] =
                (uint32_t(*)[SPADW])(smem + br * TILE_WORDS);

            float acc[2][8][4];
#pragma unroll
            for (int mi = 0; mi < 2; mi++)
#pragma unroll
                for (int nt = 0; nt < 8; nt++)
#pragma unroll
                    for (int j = 0; j < 4; j++) acc[mi][nt][j] = 0.0f;

            // MMA stream: 8 k16 steps
#pragma unroll
            for (int ks = 0; ks < 8; ks++) {
                int wk = ks * 8;
                uint32_t a[2][4];
#pragma unroll
                for (int mi = 0; mi < 2; mi++) {
                    int r = wm * 32 + mi * 16 + g;
                    a[mi][0] = As[r][wk + t];
                    a[mi][1] = As[r + 8][wk + t];
                    a[mi][2] = As[r][wk + t + 4];
                    a[mi][3] = As[r + 8][wk + t + 4];
                }
                uint32_t b[8][2];
#pragma unroll
                for (int nt = 0; nt < 8; nt++) {
                    int r = wn * 64 + nt * 8 + g;
                    b[nt][0] = Bs[r][wk + t];
                    b[nt][1] = Bs[r][wk + t + 4];
                }
#pragma unroll
                for (int mi = 0; mi < 2; mi++)
#pragma unroll
                    for (int nt = 0; nt < 8; nt++)
                        mma_f16(acc[mi][nt],
                                a[mi][0], a[mi][1], a[mi][2], a[mi][3],
                                b[nt][0], b[nt][1]);
            }

            // Epilogue: add bias, convert to fp16, store half2
#pragma unroll
            for (int mi = 0; mi < 2; mi++) {
                int r0 = row0 + wm * 32 + mi * 16 + g;
                int r1 = r0 + 8;
#pragma unroll
                for (int nt = 0; nt < 8; nt++) {
                    int c = wn * 64 + nt * 8 + 2 * t;
                    float bx = __ldg(bias + c), by = __ldg(bias + c + 1);
                    if (r0 < n) {
                        __half2 v0 = __floats2half2_rn(acc[mi][nt][0] + bx,
                                                       acc[mi][nt][1] + by);
                        *(__half2*)(out + (size_t)r0 * DIMH + c) = v0;
                    }
                    if (r1 < n) {
                        __half2 v1 = __floats2half2_rn(acc[mi][nt][2] + bx,
                                                       acc[mi][nt][3] + by);
                        *(__half2*)(out + (size_t)r1 * DIMH + c) = v1;
                    }
                }
            }
        }
        __syncthreads();   // all reads of As done before next tile's fill
    }
}

// ---------------------------------------------------------------------------
// Kernel 2 (FUSED): warp per edge.  fp16 Q/K/V loads, fp32 math, REDG out.
// ---------------------------------------------------------------------------
__global__ __launch_bounds__(256)
void fused_edge(const int* __restrict__ ei,
                const float* __restrict__ ebias,
                int E_, float* __restrict__ out_h) {
    int e    = (blockIdx.x * blockDim.x + threadIdx.x) >> 5;
    int lane = threadIdx.x & 31;
    if (e >= E_) return;

    int src = __ldg(ei + e);
    int dst = __ldg(ei + E_ + e);

    __half2 q2[2], k2[2];
    *(uint2*)q2 = *(const uint2*)(g_Q + (size_t)dst * DIMH + lane * 4);
    *(uint2*)k2 = *(const uint2*)(g_K + (size_t)src * DIMH + lane * 4);

    float2 qa = __half22float2(q2[0]), qb = __half22float2(q2[1]);
    float2 ka = __half22float2(k2[0]), kb = __half22float2(k2[1]);

    float p = qa.x * ka.x + qa.y * ka.y + qb.x * kb.x + qb.y * kb.y;
    p += __shfl_xor_sync(0xffffffffu, p, 1);
    p += __shfl_xor_sync(0xffffffffu, p, 2);

    int h = lane >> 2;
    float bias = __ldg(ebias + (size_t)e * NHEADS + h);
    float ex = __expf(p * 0.25f + bias);

    if ((lane & 3) == 0) {
        g_ex[(size_t)e * NHEADS + h] = ex;
        red_add_f32(g_segsum + (size_t)dst * NHEADS + h, ex);
    }

    __half2 v2[2];
    *(uint2*)v2 = *(const uint2*)(g_V + (size_t)src * DIMH + lane * 4);
    float2 va = __half22float2(v2[0]), vb = __half22float2(v2[1]);

    float4 v = make_float4(va.x * ex, va.y * ex, vb.x * ex, vb.y * ex);
    red_add_v4(out_h + (size_t)dst * DIMH + lane * 4, v);
}

// ---------------------------------------------------------------------------
// Kernel 3 (merged finalize): normalize h + write alpha
// ---------------------------------------------------------------------------
__global__ void finalize(const int* __restrict__ ei, int E_, int n,
                         float* __restrict__ out_h,
                         float* __restrict__ out_alpha) {
    int t = blockIdx.x * blockDim.x + threadIdx.x;

    if (t < n * 32) {
        int i = t >> 5;
        int c4 = t & 31;
        float s = g_segsum[(size_t)i * NHEADS + (c4 >> 2)];
        float inv = 1.0f / s;
        float4 v = *(float4*)(out_h + (size_t)i * DIMH + c4 * 4);
        v.x *= inv; v.y *= inv; v.z *= inv; v.w *= inv;
        *(float4*)(out_h + (size_t)i * DIMH + c4 * 4) = v;
    }

    if (t < E_) {
        int dst = __ldg(ei + E_ + t);
        float4 e0 = *(const float4*)(g_ex + (size_t)t * NHEADS);
        float4 e1 = *(const float4*)(g_ex + (size_t)t * NHEADS + 4);
        float4 s0 = *(const float4*)(g_segsum + (size_t)dst * NHEADS);
        float4 s1 = *(const float4*)(g_segsum + (size_t)dst * NHEADS + 4);

        e0.x /= s0.x; e0.y /= s0.y; e0.z /= s0.z; e0.w /= s0.w;
        e1.x /= s1.x; e1.y /= s1.y; e1.z /= s1.z; e1.w /= s1.w;

        *(float4*)(out_alpha + (size_t)t * NHEADS)     = e0;
        *(float4*)(out_alpha + (size_t)t * NHEADS + 4) = e1;
    }
}

// ---------------------------------------------------------------------------
// Launch
// ---------------------------------------------------------------------------
extern "C" void kernel_launch(void* const* d_in, const int* in_sizes, int n_in,
                              void* d_out, int out_size) {
    const float* x     = (const float*)d_in[0];
    const int*   ei    = (const int*)d_in[1];
    const float* ebias = (const float*)d_in[2];
    const float* WQ    = (const float*)d_in[3];
    const float* bQ    = (const float*)d_in[4];
    const float* WK    = (const float*)d_in[5];
    const float* bK    = (const float*)d_in[6];
    const float* WV    = (const float*)d_in[7];
    const float* bV    = (const float*)d_in[8];

    int n = in_sizes[0] / DIMH;     // 50000
    int e = in_sizes[1] / 2;        // 800000

    float* out_h = (float*)d_out;
    float* out_alpha = out_h + (size_t)n * DIMH;

    // 1) QKV projections (fp16 mma.sync, shared-A 3-branch) + fused init
    {
        cudaFuncSetAttribute(gemm_qkv_mma,
                             cudaFuncAttributeMaxDynamicSharedMemorySize,
                             SMEM_BYTES);
        gemm_qkv_mma<<<GRID_X, 256, SMEM_BYTES>>>(
            x, WQ, bQ, WK, bK, WV, bV, n, out_h);
    }
    // 2) fused edge pass
    {
        long long threads = (long long)e * 32;
        int blocks = (int)((threads + 255) / 256);
        fused_edge<<<blocks, 256>>>(ei, ebias, e, out_h);
    }
    // 3) finalize: normalize h + write alpha
    {
        int total = n * 32 > e ? n * 32 : e;
        int blocks = (total + 255) / 256;
        finalize<<<blocks, 256>>>(ei, e, n, out_h, out_alpha);
    }
}

// round 16
// speedup vs baseline: 1.1694x; 1.0346x over previous
#include <cuda_runtime.h>
#include <cuda_bf16.h>
#include <cuda_fp16.h>
#include <cstdint>

#define NMAX 50000
#define EMAX 800000
#define DIMH 128
#define NHEADS 8
#define HEADDIM 16

// ---------------------------------------------------------------------------
// Scratch (fp16 QKV + fp16 ex to cut L2 bytes; fp32 accumulators)
// ---------------------------------------------------------------------------
__device__ __half g_Q[(size_t)NMAX * DIMH];
__device__ __half g_K[(size_t)NMAX * DIMH];
__device__ __half g_V[(size_t)NMAX * DIMH];
__device__ __half g_ex[(size_t)EMAX * NHEADS];
__device__ float  g_segsum[(size_t)NMAX * NHEADS];

// ---------------------------------------------------------------------------
// Helpers
// ---------------------------------------------------------------------------
__device__ __forceinline__ void red_add_v4(float* addr, float4 v) {
    asm volatile("red.global.add.v4.f32 [%0], {%1, %2, %3, %4};"
                 :: "l"(addr), "f"(v.x), "f"(v.y), "f"(v.z), "f"(v.w) : "memory");
}
__device__ __forceinline__ void red_add_f32(float* addr, float v) {
    asm volatile("red.global.add.f32 [%0], %1;" :: "l"(addr), "f"(v) : "memory");
}
// fp16 mma m16n8k16: A row-major (4 x half2), B col-major (2 x half2), C fp32
__device__ __forceinline__ void mma_f16(float (&c)[4],
                                        uint32_t a0, uint32_t a1,
                                        uint32_t a2, uint32_t a3,
                                        uint32_t b0, uint32_t b1) {
    asm volatile("mma.sync.aligned.m16n8k16.row.col.f32.f16.f16.f32 "
                 "{%0,%1,%2,%3}, {%4,%5,%6,%7}, {%8,%9}, {%0,%1,%2,%3};"
                 : "+f"(c[0]), "+f"(c[1]), "+f"(c[2]), "+f"(c[3])
                 : "r"(a0), "r"(a1), "r"(a2), "r"(a3), "r"(b0), "r"(b1));
}
__device__ __forceinline__ uint32_t pack_half2(float x, float y) {
    __half2 h = __floats2half2_rn(x, y);
    return *(uint32_t*)&h;
}

// ---------------------------------------------------------------------------
// Kernel 1: fp16 mma.sync GEMM (m16n8k16), PERSISTENT-W, reg-capped
// (exact R14 shape: best measured at 34.0us, 2 CTAs/SM).
// grid (196, 3): each CTA fills its W tile ONCE, loops over M-tiles,
// refilling only the A (x) tile.
// Tile layout: [128 rows][68 words]; conflict-free reads (bank 4g+t) and
// fills (16-lane phase covers banks 0..31 once).
// Q-branch CTAs also zero their out_h slice + segsum (fused init).
// ---------------------------------------------------------------------------
#define SPADW 68        // words per row (64 data + 4 pad)
#define TILE_WORDS (128 * SPADW)
#define SMEM_BYTES (2 * TILE_WORDS * 4)
#define GRID_X 196

__global__ __launch_bounds__(256, 2)
void gemm_qkv_mma(const float* __restrict__ x,
                  const float* __restrict__ WQ, const float* __restrict__ bQ,
                  const float* __restrict__ WK, const float* __restrict__ bK,
                  const float* __restrict__ WV, const float* __restrict__ bV,
                  int n, float* __restrict__ out_h) {
    const float* W;
    const float* bias;
    __half* out;
    if (blockIdx.y == 0)      { W = WQ; bias = bQ; out = g_Q; }
    else if (blockIdx.y == 1) { W = WK; bias = bK; out = g_K; }
    else                      { W = WV; bias = bV; out = g_V; }

    extern __shared__ uint32_t smem[];
    uint32_t (*Bs)[SPADW] = (uint32_t(*)[SPADW])smem;
    uint32_t (*As)[SPADW] = (uint32_t(*)[SPADW])(smem + TILE_WORDS);

    const int tid  = threadIdx.x;
    const int wid  = tid >> 5;
    const int lane = tid & 31;
    const int g    = lane >> 2;
    const int t    = lane & 3;
    const int wm   = wid & 3;        // M group: rows [wm*32, wm*32+32)
    const int wn   = wid >> 2;       // N group: cols [wn*64, wn*64+64)
    const int ntiles = (n + 127) >> 7;

    // --- fill W tile ONCE (128 rows x 32 float4 = 4096; 16 per thread)
#pragma unroll
    for (int i = 0; i < 16; i++) {
        int u2  = tid + i * 256;
        int row = u2 >> 5;
        int c   = u2 & 31;
        float4 w = *(const float4*)(W + (size_t)row * DIMH + c * 4);
        *(uint2*)&Bs[row][c * 2] =
            make_uint2(pack_half2(w.x, w.y), pack_half2(w.z, w.w));
    }

    for (int ti = blockIdx.x; ti < ntiles; ti += GRID_X) {
        const int row0 = ti * 128;

        // --- fused init: Q-branch zeroes out_h rows [row0,row0+128) + segsum
        if (blockIdx.y == 0) {
            float4 z = make_float4(0.f, 0.f, 0.f, 0.f);
#pragma unroll
            for (int i = 0; i < 16; i++) {
                int idx = tid + i * 256;
                int r   = row0 + (idx >> 5);
                if (r < n)
                    *(float4*)(out_h + (size_t)r * DIMH + (idx & 31) * 4) = z;
            }
            {
                int r = row0 + (tid >> 1);
                if (r < n)
                    *(float4*)(g_segsum + (size_t)r * NHEADS + (tid & 1) * 4) = z;
            }
        }

        // --- fill A tile (x rows, fp32->fp16, zero-padded)
#pragma unroll
        for (int i = 0; i < 16; i++) {
            int u2  = tid + i * 256;
            int row = u2 >> 5;
            int c   = u2 & 31;
            int gr  = row0 + row;
            float4 a = make_float4(0.f, 0.f, 0.f, 0.f);
            if (gr < n) a = *(const float4*)(x + (size_t)gr * DIMH + c * 4);
            *(uint2*)&As[row][c * 2] =
                make_uint2(pack_half2(a.x, a.y), pack_half2(a.z, a.w));
        }
        __syncthreads();

        float acc[2][8][4];
#pragma unroll
        for (int mi = 0; mi < 2; mi++)
#pragma unroll
            for (int nt = 0; nt < 8; nt++)
#pragma unroll
                for (int j = 0; j < 4; j++) acc[mi][nt][j] = 0.0f;

        // --- MMA stream: 8 k16 steps
#pragma unroll
        for (int ks = 0; ks < 8; ks++) {
            int wk = ks * 8;
            uint32_t a[2][4];
#pragma unroll
            for (int mi = 0; mi < 2; mi++) {
                int r = wm * 32 + mi * 16 + g;
                a[mi][0] = As[r][wk + t];
                a[mi][1] = As[r + 8][wk + t];
                a[mi][2] = As[r][wk + t + 4];
                a[mi][3] = As[r + 8][wk + t + 4];
            }
            uint32_t b[8][2];
#pragma unroll
            for (int nt = 0; nt < 8; nt++) {
                int r = wn * 64 + nt * 8 + g;
                b[nt][0] = Bs[r][wk + t];
                b[nt][1] = Bs[r][wk + t + 4];
            }
#pragma unroll
            for (int mi = 0; mi < 2; mi++)
#pragma unroll
                for (int nt = 0; nt < 8; nt++)
                    mma_f16(acc[mi][nt],
                            a[mi][0], a[mi][1], a[mi][2], a[mi][3],
                            b[nt][0], b[nt][1]);
        }

        // Epilogue: add bias, convert to fp16, store half2
#pragma unroll
        for (int mi = 0; mi < 2; mi++) {
            int r0 = row0 + wm * 32 + mi * 16 + g;
            int r1 = r0 + 8;
#pragma unroll
            for (int nt = 0; nt < 8; nt++) {
                int c = wn * 64 + nt * 8 + 2 * t;
                float bx = __ldg(bias + c), by = __ldg(bias + c + 1);
                if (r0 < n) {
                    __half2 v0 = __floats2half2_rn(acc[mi][nt][0] + bx,
                                                   acc[mi][nt][1] + by);
                    *(__half2*)(out + (size_t)r0 * DIMH + c) = v0;
                }
                if (r1 < n) {
                    __half2 v1 = __floats2half2_rn(acc[mi][nt][2] + bx,
                                                   acc[mi][nt][3] + by);
                    *(__half2*)(out + (size_t)r1 * DIMH + c) = v1;
                }
            }
        }
        __syncthreads();   // all reads of As done before next tile's fill
    }
}

// ---------------------------------------------------------------------------
// Kernel 2 (FUSED): warp per edge.  fp16 Q/K/V loads, fp32 math, REDG out.
// ex stored fp16 (only alpha consumes it; h path uses in-register fp32 ex).
// ---------------------------------------------------------------------------
__global__ __launch_bounds__(256)
void fused_edge(const int* __restrict__ ei,
                const float* __restrict__ ebias,
                int E_, float* __restrict__ out_h) {
    int e    = (blockIdx.x * blockDim.x + threadIdx.x) >> 5;
    int lane = threadIdx.x & 31;
    if (e >= E_) return;

    int src = __ldg(ei + e);
    int dst = __ldg(ei + E_ + e);

    __half2 q2[2], k2[2];
    *(uint2*)q2 = *(const uint2*)(g_Q + (size_t)dst * DIMH + lane * 4);
    *(uint2*)k2 = *(const uint2*)(g_K + (size_t)src * DIMH + lane * 4);

    float2 qa = __half22float2(q2[0]), qb = __half22float2(q2[1]);
    float2 ka = __half22float2(k2[0]), kb = __half22float2(k2[1]);

    float p = qa.x * ka.x + qa.y * ka.y + qb.x * kb.x + qb.y * kb.y;
    p += __shfl_xor_sync(0xffffffffu, p, 1);
    p += __shfl_xor_sync(0xffffffffu, p, 2);

    int h = lane >> 2;
    float bias = __ldg(ebias + (size_t)e * NHEADS + h);
    float ex = __expf(p * 0.25f + bias);

    if ((lane & 3) == 0) {
        g_ex[(size_t)e * NHEADS + h] = __float2half(ex);
        red_add_f32(g_segsum + (size_t)dst * NHEADS + h, ex);
    }

    __half2 v2[2];
    *(uint2*)v2 = *(const uint2*)(g_V + (size_t)src * DIMH + lane * 4);
    float2 va = __half22float2(v2[0]), vb = __half22float2(v2[1]);

    float4 v = make_float4(va.x * ex, va.y * ex, vb.x * ex, vb.y * ex);
    red_add_v4(out_h + (size_t)dst * DIMH + lane * 4, v);
}

// ---------------------------------------------------------------------------
// Kernel 3 (merged finalize): normalize h + write alpha (fp16 ex read)
// ---------------------------------------------------------------------------
__global__ void finalize(const int* __restrict__ ei, int E_, int n,
                         float* __restrict__ out_h,
                         float* __restrict__ out_alpha) {
    int t = blockIdx.x * blockDim.x + threadIdx.x;

    if (t < n * 32) {
        int i = t >> 5;
        int c4 = t & 31;
        float s = g_segsum[(size_t)i * NHEADS + (c4 >> 2)];
        float inv = 1.0f / s;
        float4 v = *(float4*)(out_h + (size_t)i * DIMH + c4 * 4);
        v.x *= inv; v.y *= inv; v.z *= inv; v.w *= inv;
        *(float4*)(out_h + (size_t)i * DIMH + c4 * 4) = v;
    }

    if (t < E_) {
        int dst = __ldg(ei + E_ + t);
        // 8 fp16 ex values in one 16B load
        __half2 exh[4];
        *(uint4*)exh = *(const uint4*)(g_ex + (size_t)t * NHEADS);
        float2 x0 = __half22float2(exh[0]), x1 = __half22float2(exh[1]);
        float2 x2 = __half22float2(exh[2]), x3 = __half22float2(exh[3]);

        float4 s0 = *(const float4*)(g_segsum + (size_t)dst * NHEADS);
        float4 s1 = *(const float4*)(g_segsum + (size_t)dst * NHEADS + 4);

        float4 a0 = make_float4(x0.x / s0.x, x0.y / s0.y,
                                x1.x / s0.z, x1.y / s0.w);
        float4 a1 = make_float4(x2.x / s1.x, x2.y / s1.y,
                                x3.x / s1.z, x3.y / s1.w);

        *(float4*)(out_alpha + (size_t)t * NHEADS)     = a0;
        *(float4*)(out_alpha + (size_t)t * NHEADS + 4) = a1;
    }
}

// ---------------------------------------------------------------------------
// Launch
// ---------------------------------------------------------------------------
extern "C" void kernel_launch(void* const* d_in, const int* in_sizes, int n_in,
                              void* d_out, int out_size) {
    const float* x     = (const float*)d_in[0];
    const int*   ei    = (const int*)d_in[1];
    const float* ebias = (const float*)d_in[2];
    const float* WQ    = (const float*)d_in[3];
    const float* bQ    = (const float*)d_in[4];
    const float* WK    = (const float*)d_in[5];
    const float* bK    = (const float*)d_in[6];
    const float* WV    = (const float*)d_in[7];
    const float* bV    = (const float*)d_in[8];

    int n = in_sizes[0] / DIMH;     // 50000
    int e = in_sizes[1] / 2;        // 800000

    float* out_h = (float*)d_out;
    float* out_alpha = out_h + (size_t)n * DIMH;

    // 1) QKV projections (fp16 mma.sync, persistent-W, 2 CTA/SM) + fused init
    {
        cudaFuncSetAttribute(gemm_qkv_mma,
                             cudaFuncAttributeMaxDynamicSharedMemorySize,
                             SMEM_BYTES);
        dim3 grid(GRID_X, 3);
        gemm_qkv_mma<<<grid, 256, SMEM_BYTES>>>(
            x, WQ, bQ, WK, bK, WV, bV, n, out_h);
    }
    // 2) fused edge pass
    {
        long long threads = (long long)e * 32;
        int blocks = (int)((threads + 255) / 256);
        fused_edge<<<blocks, 256>>>(ei, ebias, e, out_h);
    }
    // 3) finalize: normalize h + write alpha
    {
        int total = n * 32 > e ? n * 32 : e;
        int blocks = (total + 255) / 256;
        finalize<<<blocks, 256>>>(ei, e, n, out_h, out_alpha);
    }
}